// round 2
// baseline (speedup 1.0000x reference)
#include <cuda_runtime.h>
#include <math.h>

#define NTOK 4096
#define DIM  1024
#define FDIM 4096
#define NEXP 8

// ---------------- scratch (static device globals; no allocation allowed) ----
__device__ float g_WpT[(size_t)DIM * DIM];          // 4 MB   Wp transposed
__device__ float g_sn[NEXP * DIM];                  // 32 KB  normalized sim rows
__device__ float g_proj[(size_t)NTOK * DIM];        // 16 MB
__device__ int   g_topi[NTOK * 2];
__device__ float g_topw[NTOK * 2];
__device__ int   g_count[NEXP];
__device__ int   g_toklist[NEXP * NTOK];
__device__ float g_tokw[NEXP * NTOK];
__device__ float g_H[(size_t)NEXP * NTOK * FDIM];   // 512 MB hidden activations

// ---------------------------------------------------------------------------
__global__ void zero_kernel(float* __restrict__ out) {
    size_t i = (size_t)blockIdx.x * blockDim.x + threadIdx.x;
    if (i < (size_t)NTOK * DIM) out[i] = 0.0f;
    if (i < NEXP) g_count[i] = 0;
}

__global__ void transpose_kernel(const float* __restrict__ Wp) {
    int idx = blockIdx.x * blockDim.x + threadIdx.x;   // 1M threads
    int i = idx >> 10;          // row of WpT
    int o = idx & (DIM - 1);    // col of WpT
    g_WpT[idx] = Wp[o * DIM + i];
}

__global__ void normsim_kernel(const float* __restrict__ sim) {
    int w = threadIdx.x >> 5, lane = threadIdx.x & 31;
    if (w >= NEXP) return;
    float ss = 0.0f;
    for (int k = lane; k < DIM; k += 32) { float v = sim[w * DIM + k]; ss += v * v; }
    #pragma unroll
    for (int off = 16; off; off >>= 1) ss += __shfl_xor_sync(0xffffffffu, ss, off);
    float inv = 1.0f / fmaxf(sqrtf(ss), 1e-12f);
    for (int k = lane; k < DIM; k += 32) g_sn[w * DIM + k] = sim[w * DIM + k] * inv;
}

// one warp per token: norm of proj row, 8 dots, top-2, softmax
__global__ void gate_kernel(const float* __restrict__ temp) {
    int w = threadIdx.x >> 5, lane = threadIdx.x & 31;
    int t = blockIdx.x * 8 + w;
    if (t >= NTOK) return;
    const float* pr = g_proj + (size_t)t * DIM;
    float ss = 0.0f, d[NEXP];
    #pragma unroll
    for (int e = 0; e < NEXP; e++) d[e] = 0.0f;
    for (int k = lane; k < DIM; k += 32) {
        float p = pr[k];
        ss += p * p;
        #pragma unroll
        for (int e = 0; e < NEXP; e++) d[e] += p * g_sn[e * DIM + k];
    }
    #pragma unroll
    for (int off = 16; off; off >>= 1) {
        ss += __shfl_xor_sync(0xffffffffu, ss, off);
        #pragma unroll
        for (int e = 0; e < NEXP; e++) d[e] += __shfl_xor_sync(0xffffffffu, d[e], off);
    }
    if (lane == 0) {
        float inv  = 1.0f / fmaxf(sqrtf(ss), 1e-12f);
        float tinv = 1.0f / temp[0];
        float sc[NEXP];
        #pragma unroll
        for (int e = 0; e < NEXP; e++) sc[e] = d[e] * inv * tinv;
        int i0 = 0; float v0 = sc[0];
        #pragma unroll
        for (int e = 1; e < NEXP; e++) if (sc[e] > v0) { v0 = sc[e]; i0 = e; }
        int i1 = -1; float v1 = -1e30f;
        #pragma unroll
        for (int e = 0; e < NEXP; e++) if (e != i0 && sc[e] > v1) { v1 = sc[e]; i1 = e; }
        float e1 = expf(v1 - v0);
        float w0 = 1.0f / (1.0f + e1);
        g_topi[t * 2] = i0;  g_topi[t * 2 + 1] = i1;
        g_topw[t * 2] = w0;  g_topw[t * 2 + 1] = e1 * w0;
    }
}

__global__ void route_kernel() {
    int t = blockIdx.x * blockDim.x + threadIdx.x;
    if (t >= NTOK) return;
    #pragma unroll
    for (int k = 0; k < 2; k++) {
        int e = g_topi[t * 2 + k];
        int pos = atomicAdd(&g_count[e], 1);
        g_toklist[e * NTOK + pos] = t;
        g_tokw[e * NTOK + pos]    = g_topw[t * 2 + k];
    }
}

__device__ __forceinline__ float gelu_exact(float v) {
    return 0.5f * v * (1.0f + erff(v * 0.70710678118654752440f));
}

// ---------------------------------------------------------------------------
// Shared 128x128x8 fp32 SGEMM core, 256 threads, 8x8 micro-tile.
// MODE 0: proj = x @ WpT                      (writes g_proj)
// MODE 1: H = gelu(gather(x) @ W1[e] + b1[e]) (writes g_H, rows gathered)
// MODE 2: out += w * (H[e] @ W2[e] + b2[e])   (atomicAdd scatter)
// ---------------------------------------------------------------------------
template<int MODE>
__global__ __launch_bounds__(256)
void moe_gemm(const float* __restrict__ Abase, const float* __restrict__ Wbase,
              const float* __restrict__ bias, float* __restrict__ out) {
    constexpr int BM = 128, BN = 128, BK = 8;
    int e = blockIdx.z;
    int M, N, K;
    const float* A; const float* Bm; const int* rows = nullptr;
    if (MODE == 0)      { M = NTOK;       N = DIM;  K = DIM;  A = Abase; Bm = g_WpT; }
    else if (MODE == 1) { M = g_count[e]; N = FDIM; K = DIM;  A = Abase;
                          Bm = Wbase + (size_t)e * DIM * FDIM; rows = g_toklist + e * NTOK; }
    else                { M = g_count[e]; N = DIM;  K = FDIM;
                          A = g_H + (size_t)e * NTOK * FDIM;
                          Bm = Wbase + (size_t)e * FDIM * DIM; }
    int m0 = blockIdx.y * BM;
    if (m0 >= M) return;
    int n0 = blockIdx.x * BN;

    __shared__ float As[BK][BM];
    __shared__ float Bs[BK][BN];

    int tid  = threadIdx.x;
    int arow = tid >> 1;            // 0..127
    int acol = (tid & 1) * 4;       // 0 or 4
    int brow = tid >> 5;            // 0..7
    int bcol = (tid & 31) * 4;      // 0..124

    int  aj = m0 + arow;
    bool avalid = aj < M;
    int  agr = 0;
    if (avalid) agr = (MODE == 1) ? rows[aj] : aj;
    const float* aptr = A  + (size_t)agr * K + acol;
    const float* bptr = Bm + (size_t)brow * N + n0 + bcol;

    float acc[8][8];
    #pragma unroll
    for (int i = 0; i < 8; i++)
        #pragma unroll
        for (int j = 0; j < 8; j++) acc[i][j] = 0.0f;

    int tx = tid & 15, ty = tid >> 4;

    for (int k0 = 0; k0 < K; k0 += BK) {
        float4 av = avalid ? *(const float4*)(aptr + k0) : make_float4(0, 0, 0, 0);
        float4 bv = *(const float4*)(bptr + (size_t)k0 * N);
        As[acol + 0][arow] = av.x; As[acol + 1][arow] = av.y;
        As[acol + 2][arow] = av.z; As[acol + 3][arow] = av.w;
        *(float4*)&Bs[brow][bcol] = bv;
        __syncthreads();
        #pragma unroll
        for (int kk = 0; kk < BK; kk++) {
            float a[8], b[8];
            *(float4*)&a[0] = *(const float4*)&As[kk][ty * 8];
            *(float4*)&a[4] = *(const float4*)&As[kk][ty * 8 + 4];
            *(float4*)&b[0] = *(const float4*)&Bs[kk][tx * 8];
            *(float4*)&b[4] = *(const float4*)&Bs[kk][tx * 8 + 4];
            #pragma unroll
            for (int i = 0; i < 8; i++)
                #pragma unroll
                for (int j = 0; j < 8; j++)
                    acc[i][j] += a[i] * b[j];
        }
        __syncthreads();
    }

    // epilogue
    if (MODE == 0) {
        #pragma unroll
        for (int i = 0; i < 8; i++) {
            int m = m0 + ty * 8 + i;
            if (m < M) {
                float* o = g_proj + (size_t)m * DIM + n0 + tx * 8;
                float4 v0 = make_float4(acc[i][0], acc[i][1], acc[i][2], acc[i][3]);
                float4 v1 = make_float4(acc[i][4], acc[i][5], acc[i][6], acc[i][7]);
                *(float4*)&o[0] = v0; *(float4*)&o[4] = v1;
            }
        }
    } else if (MODE == 1) {
        const float* bb = bias + (size_t)e * FDIM + n0 + tx * 8;
        float bv[8];
        #pragma unroll
        for (int j = 0; j < 8; j++) bv[j] = bb[j];
        #pragma unroll
        for (int i = 0; i < 8; i++) {
            int m = m0 + ty * 8 + i;
            if (m < M) {
                float* o = g_H + ((size_t)e * NTOK + m) * FDIM + n0 + tx * 8;
                float r[8];
                #pragma unroll
                for (int j = 0; j < 8; j++) r[j] = gelu_exact(acc[i][j] + bv[j]);
                *(float4*)&o[0] = make_float4(r[0], r[1], r[2], r[3]);
                *(float4*)&o[4] = make_float4(r[4], r[5], r[6], r[7]);
            }
        }
    } else {
        const float* bb = bias + (size_t)e * DIM + n0 + tx * 8;
        float bv[8];
        #pragma unroll
        for (int j = 0; j < 8; j++) bv[j] = bb[j];
        #pragma unroll
        for (int i = 0; i < 8; i++) {
            int m = m0 + ty * 8 + i;
            if (m < M) {
                float wv = g_tokw[e * NTOK + m];
                int tok  = g_toklist[e * NTOK + m];
                float* o = out + (size_t)tok * DIM + n0 + tx * 8;
                #pragma unroll
                for (int j = 0; j < 8; j++)
                    atomicAdd(&o[j], wv * (acc[i][j] + bv[j]));
            }
        }
    }
}

// ---------------------------------------------------------------------------
extern "C" void kernel_launch(void* const* d_in, const int* in_sizes, int n_in,
                              void* d_out, int out_size) {
    const float* x    = (const float*)d_in[0];
    const float* Wp   = (const float*)d_in[1];
    const float* sim  = (const float*)d_in[2];
    const float* temp = (const float*)d_in[3];
    const float* W1   = (const float*)d_in[4];
    const float* b1   = (const float*)d_in[5];
    const float* W2   = (const float*)d_in[6];
    const float* b2   = (const float*)d_in[7];
    float* out = (float*)d_out;

    zero_kernel<<<(NTOK * DIM + 255) / 256, 256>>>(out);
    transpose_kernel<<<(DIM * DIM) / 256, 256>>>(Wp);
    normsim_kernel<<<1, 256>>>(sim);

    dim3 g0(DIM / 128, NTOK / 128, 1);          // proj: 8 x 32
    moe_gemm<0><<<g0, 256>>>(x, nullptr, nullptr, nullptr);

    gate_kernel<<<NTOK / 8, 256>>>(temp);
    route_kernel<<<NTOK / 256, 256>>>();

    dim3 g1(FDIM / 128, NTOK / 128, NEXP);      // layer1: 32 x 32 x 8
    moe_gemm<1><<<g1, 256>>>(x, W1, b1, nullptr);

    dim3 g2(DIM / 128, NTOK / 128, NEXP);       // layer2: 8 x 32 x 8
    moe_gemm<2><<<g2, 256>>>(nullptr, W2, b2, out);
}

// round 4
// speedup vs baseline: 2.7468x; 2.7468x over previous
#include <cuda_runtime.h>
#include <math.h>
#include <stdint.h>

#define NTOK 4096
#define DIM  1024
#define FDIM 4096
#define NEXP 8

// ---------------- scratch (static device globals; no allocation allowed) ----
__device__ float g_sn[NEXP * DIM];
__device__ float g_M[NEXP * DIM];            // fp32-exact gate numerator matrix
__device__ float g_norm2[NTOK];              // |proj row|^2 (tf32-grade; scale only)
__device__ int   g_topi[NTOK * 2];
__device__ float g_topw[NTOK * 2];
__device__ int   g_count[NEXP];
__device__ int   g_toklist[NEXP * NTOK];
__device__ float g_tokw[NEXP * NTOK];
// H stored TRANSPOSED: Ht[e][F][m]  (m = compacted token index, stride NTOK)
__device__ float g_H[(size_t)NEXP * FDIM * NTOK];

// ---------------- helpers ---------------------------------------------------
__device__ __forceinline__ uint32_t cvt_tf32(float x) {
    uint32_t r;
    asm("cvt.rna.tf32.f32 %0, %1;" : "=r"(r) : "f"(x));
    return r;
}
__device__ __forceinline__ void mma_tf32(float* d, const uint32_t* a, const uint32_t* b) {
    asm volatile(
        "mma.sync.aligned.m16n8k8.row.col.f32.tf32.tf32.f32 "
        "{%0,%1,%2,%3}, {%4,%5,%6,%7}, {%8,%9}, {%0,%1,%2,%3};"
        : "+f"(d[0]), "+f"(d[1]), "+f"(d[2]), "+f"(d[3])
        : "r"(a[0]), "r"(a[1]), "r"(a[2]), "r"(a[3]), "r"(b[0]), "r"(b[1]));
}
__device__ __forceinline__ float gelu_exact(float v) {
    return 0.5f * v * (1.0f + erff(v * 0.70710678118654752440f));
}

// ---------------------------------------------------------------------------
__global__ void zero_kernel(float* __restrict__ out) {
    size_t i = (size_t)blockIdx.x * blockDim.x + threadIdx.x;
    if (i < (size_t)NTOK * DIM) out[i] = 0.0f;
    if (i < NTOK) g_norm2[i] = 0.0f;
    if (i < NEXP) g_count[i] = 0;
}

__global__ void normsim_kernel(const float* __restrict__ sim) {
    int w = threadIdx.x >> 5, lane = threadIdx.x & 31;
    if (w >= NEXP) return;
    float ss = 0.0f;
    for (int k = lane; k < DIM; k += 32) { float v = sim[w * DIM + k]; ss += v * v; }
    #pragma unroll
    for (int off = 16; off; off >>= 1) ss += __shfl_xor_sync(0xffffffffu, ss, off);
    float inv = 1.0f / fmaxf(sqrtf(ss), 1e-12f);
    for (int k = lane; k < DIM; k += 32) g_sn[w * DIM + k] = sim[w * DIM + k] * inv;
}

// M[e][i] = sum_o Wp[o][i] * sn[e][o]   (fp32-exact gate numerators)
__global__ void gateM_kernel(const float* __restrict__ Wp) {
    int e = blockIdx.x;
    int i0 = threadIdx.x * 4;
    float4 acc = make_float4(0, 0, 0, 0);
    #pragma unroll 4
    for (int o = 0; o < DIM; o++) {
        float s = g_sn[e * DIM + o];
        float4 w = *(const float4*)(Wp + (size_t)o * DIM + i0);
        acc.x += s * w.x; acc.y += s * w.y; acc.z += s * w.z; acc.w += s * w.w;
    }
    *(float4*)(g_M + e * DIM + i0) = acc;
}

// one warp per token: fp32 dots x.M_e; |p| from tf32 norm; top2+softmax
__global__ void gate2_kernel(const float* __restrict__ x, const float* __restrict__ temp) {
    __shared__ float sM[NEXP][DIM];
    int tid = threadIdx.x;
    for (int i = tid; i < NEXP * DIM; i += 256) ((float*)sM)[i] = g_M[i];
    __syncthreads();
    int w = tid >> 5, lane = tid & 31;
    int t = blockIdx.x * 8 + w;
    const float4* xr = (const float4*)(x + (size_t)t * DIM);
    float acc[NEXP];
    #pragma unroll
    for (int e = 0; e < NEXP; e++) acc[e] = 0.0f;
    for (int k4 = lane; k4 < DIM / 4; k4 += 32) {
        float4 xv = xr[k4];
        #pragma unroll
        for (int e = 0; e < NEXP; e++) {
            float4 mv = *(const float4*)&sM[e][k4 * 4];
            acc[e] += xv.x * mv.x + xv.y * mv.y + xv.z * mv.z + xv.w * mv.w;
        }
    }
    #pragma unroll
    for (int off = 16; off; off >>= 1)
        #pragma unroll
        for (int e = 0; e < NEXP; e++) acc[e] += __shfl_xor_sync(0xffffffffu, acc[e], off);
    if (lane == 0) {
        float pn   = sqrtf(g_norm2[t]);
        float inv  = 1.0f / fmaxf(pn, 1e-12f);
        float tinv = 1.0f / temp[0];
        float sc[NEXP];
        #pragma unroll
        for (int e = 0; e < NEXP; e++) sc[e] = acc[e] * inv * tinv;
        int i0 = 0; float v0 = sc[0];
        #pragma unroll
        for (int e = 1; e < NEXP; e++) if (sc[e] > v0) { v0 = sc[e]; i0 = e; }
        int i1 = -1; float v1 = -1e30f;
        #pragma unroll
        for (int e = 0; e < NEXP; e++) if (e != i0 && sc[e] > v1) { v1 = sc[e]; i1 = e; }
        float e1 = expf(v1 - v0);
        float w0 = 1.0f / (1.0f + e1);
        g_topi[t * 2] = i0;  g_topi[t * 2 + 1] = i1;
        g_topw[t * 2] = w0;  g_topw[t * 2 + 1] = e1 * w0;
    }
}

__global__ void route_kernel() {
    int t = blockIdx.x * blockDim.x + threadIdx.x;
    if (t >= NTOK) return;
    #pragma unroll
    for (int k = 0; k < 2; k++) {
        int e = g_topi[t * 2 + k];
        int pos = atomicAdd(&g_count[e], 1);
        g_toklist[e * NTOK + pos] = t;
        g_tokw[e * NTOK + pos]    = g_topw[t * 2 + k];
    }
}

// ---------------------------------------------------------------------------
// tf32 mma.sync GEMM, tile 128(R) x 128(C) x 32, 8 warps (4R x 2C), 2-buf.
// R = A-operand 16-dim, C = B-operand 8-dim.
// MODE 0: R=tokens, C=proj-features. A=x[m][k], B=Wp[n][k] (both native).
//         epilogue: row-norm^2 partials -> atomicAdd g_norm2.
// MODE 1: R=F, C=tokens. A=W1[k][F] native, B=x[gather m][k] native.
//         epilogue: Ht[e][F][m] = gelu(acc + b1[F]).
// MODE 2: R=d, C=tokens. A=W2[k][d] native, B=Ht[e][k=F][m] native.
//         epilogue: out[tok][d] += wv * (acc + b2[d])  (atomicAdd).
// ---------------------------------------------------------------------------
template<int MODE>
__global__ __launch_bounds__(256)
void moe_mma(const float* __restrict__ x, const float* __restrict__ Wglob,
             const float* __restrict__ bias, float* __restrict__ out) {
    constexpr int K   = (MODE == 2) ? FDIM : DIM;
    constexpr int ND  = (MODE == 1) ? FDIM : DIM;   // A-operand feature dim (W row width)
    constexpr int A_KC = (MODE != 0);               // A tile layout [k][r] stride 136
    constexpr int B_KC = (MODE == 2);               // B tile layout [k][c] stride 136
    constexpr int A_SZ = A_KC ? 32 * 136 * 4 : 128 * 36 * 4;
    constexpr int B_SZ = B_KC ? 32 * 136 * 4 : 128 * 36 * 4;
    constexpr int OFF_A0 = 512;
    constexpr int OFF_B0 = OFF_A0 + A_SZ;
    constexpr int OFF_A1 = OFF_B0 + B_SZ;
    constexpr int OFF_B1 = OFF_A1 + A_SZ;

    extern __shared__ char sm[];
    const int tid  = threadIdx.x;
    const int lane = tid & 31;
    const int wid  = tid >> 5;
    const int gid  = lane >> 2;
    const int tig  = lane & 3;
    const int R_warp = (wid & 3) * 32;
    const int C_warp = (wid >> 2) * 64;
    const int e  = blockIdx.z;

    const int R0 = (MODE == 0 ? blockIdx.y : blockIdx.x) * 128;
    const int C0 = (MODE == 0 ? blockIdx.x : blockIdx.y) * 128;
    int M = NTOK;
    const int* rows = nullptr;
    const float* We = Wglob;
    if (MODE != 0) {
        M = g_count[e];
        if (C0 >= M) return;
        rows = g_toklist + e * NTOK;
        We = Wglob + (size_t)e * K * ND;
    }
    if (MODE != 0 && tid < 128)
        ((float*)sm)[tid] = bias[(size_t)e * ND + R0 + tid];

    // ---- global-load index setup ----
    // A-operand
    const float* aptr = nullptr;
    int kr = 0, nq = 0, arow = 0, ah = 0;
    if (MODE == 0) {
        arow = tid >> 1; ah = (tid & 1) * 16;
        aptr = x + (size_t)(R0 + arow) * DIM + ah;
    } else {
        kr = tid >> 5; nq = (tid & 31) * 4;
        aptr = We + (size_t)kr * ND + R0 + nq;
    }
    // B-operand
    const float* bptr = nullptr;
    int brow = 0, bh = 0, fr = 0, mq = 0;
    if (MODE == 0) {
        brow = tid >> 1; bh = (tid & 1) * 16;
        bptr = Wglob + (size_t)(C0 + brow) * DIM + bh;
    } else if (MODE == 1) {
        brow = tid >> 1; bh = (tid & 1) * 16;
        int gm = C0 + brow;
        int gr = (gm < M) ? rows[gm] : 0;
        bptr = x + (size_t)gr * DIM + bh;
    } else {
        fr = tid >> 5; mq = (tid & 31) * 4;
        bptr = g_H + ((size_t)e * FDIM + fr) * NTOK + C0 + mq;
    }

    float acc[2][8][4];
    #pragma unroll
    for (int i = 0; i < 2; i++)
        #pragma unroll
        for (int j = 0; j < 8; j++)
            #pragma unroll
            for (int q = 0; q < 4; q++) acc[i][j][q] = 0.0f;

    float4 rA[4], rB[4];
    // prefetch chunk 0
    #pragma unroll
    for (int i = 0; i < 4; i++) {
        if (MODE == 0) rA[i] = *(const float4*)(aptr + 4 * i);
        else           rA[i] = *(const float4*)(aptr + (size_t)(8 * i) * ND);
    }
    #pragma unroll
    for (int i = 0; i < 4; i++) {
        if (MODE == 2) rB[i] = *(const float4*)(bptr + (size_t)(8 * i) * NTOK);
        else           rB[i] = *(const float4*)(bptr + 4 * i);
    }

    const int nch = K / 32;
    for (int c = 0; c < nch; ++c) {
        const int b = c & 1;
        uint32_t* sA = (uint32_t*)(sm + (b ? OFF_A1 : OFF_A0));
        uint32_t* sB = (uint32_t*)(sm + (b ? OFF_B1 : OFF_B0));
        // ---- store prefetched chunk (cvt to tf32) ----
        #pragma unroll
        for (int i = 0; i < 4; i++) {
            uint32_t vx = cvt_tf32(rA[i].x), vy = cvt_tf32(rA[i].y),
                     vz = cvt_tf32(rA[i].z), vw = cvt_tf32(rA[i].w);
            uint32_t* d = A_KC ? &sA[(kr + 8 * i) * 136 + nq]
                               : &sA[arow * 36 + ah + 4 * i];
            d[0] = vx; d[1] = vy; d[2] = vz; d[3] = vw;
        }
        #pragma unroll
        for (int i = 0; i < 4; i++) {
            uint32_t vx = cvt_tf32(rB[i].x), vy = cvt_tf32(rB[i].y),
                     vz = cvt_tf32(rB[i].z), vw = cvt_tf32(rB[i].w);
            uint32_t* d = B_KC ? &sB[(fr + 8 * i) * 136 + mq]
                               : &sB[brow * 36 + bh + 4 * i];
            d[0] = vx; d[1] = vy; d[2] = vz; d[3] = vw;
        }
        __syncthreads();
        // ---- prefetch next chunk ----
        if (c + 1 < nch) {
            const int k0 = (c + 1) * 32;
            #pragma unroll
            for (int i = 0; i < 4; i++) {
                if (MODE == 0) rA[i] = *(const float4*)(aptr + k0 + 4 * i);
                else           rA[i] = *(const float4*)(aptr + (size_t)(k0 + 8 * i) * ND);
            }
            #pragma unroll
            for (int i = 0; i < 4; i++) {
                if (MODE == 2)      rB[i] = *(const float4*)(bptr + (size_t)(k0 + 8 * i) * NTOK);
                else                rB[i] = *(const float4*)(bptr + k0 + 4 * i);
            }
        }
        // ---- compute ----
        #pragma unroll
        for (int kb = 0; kb < 4; kb++) {
            const int k = kb * 8 + tig;
            uint32_t af[2][4];
            #pragma unroll
            for (int rt = 0; rt < 2; rt++) {
                const int r = R_warp + rt * 16 + gid;
                if (A_KC) {
                    af[rt][0] = sA[k * 136 + r];       af[rt][1] = sA[k * 136 + r + 8];
                    af[rt][2] = sA[(k + 4) * 136 + r]; af[rt][3] = sA[(k + 4) * 136 + r + 8];
                } else {
                    af[rt][0] = sA[r * 36 + k];        af[rt][1] = sA[(r + 8) * 36 + k];
                    af[rt][2] = sA[r * 36 + k + 4];    af[rt][3] = sA[(r + 8) * 36 + k + 4];
                }
            }
            #pragma unroll
            for (int ct = 0; ct < 8; ct++) {
                const int cc = C_warp + ct * 8 + gid;
                uint32_t bf[2];
                if (B_KC) { bf[0] = sB[k * 136 + cc]; bf[1] = sB[(k + 4) * 136 + cc]; }
                else      { bf[0] = sB[cc * 36 + k];  bf[1] = sB[cc * 36 + k + 4];  }
                mma_tf32(acc[0][ct], af[0], bf);
                mma_tf32(acc[1][ct], af[1], bf);
            }
        }
        __syncthreads();
    }

    // ---- epilogue ----
    const float* sBias = (const float*)sm;
    if (MODE == 0) {
        #pragma unroll
        for (int rt = 0; rt < 2; rt++) {
            float s0 = 0.0f, s1 = 0.0f;
            #pragma unroll
            for (int ct = 0; ct < 8; ct++) {
                s0 += acc[rt][ct][0] * acc[rt][ct][0] + acc[rt][ct][1] * acc[rt][ct][1];
                s1 += acc[rt][ct][2] * acc[rt][ct][2] + acc[rt][ct][3] * acc[rt][ct][3];
            }
            s0 += __shfl_xor_sync(0xffffffffu, s0, 1);
            s0 += __shfl_xor_sync(0xffffffffu, s0, 2);
            s1 += __shfl_xor_sync(0xffffffffu, s1, 1);
            s1 += __shfl_xor_sync(0xffffffffu, s1, 2);
            if (tig == 0) {
                int r = R0 + R_warp + rt * 16 + gid;
                atomicAdd(&g_norm2[r], s0);
                atomicAdd(&g_norm2[r + 8], s1);
            }
        }
    } else if (MODE == 1) {
        #pragma unroll
        for (int rt = 0; rt < 2; rt++) {
            const int Fl = R_warp + rt * 16 + gid;
            const int F  = R0 + Fl;
            const float bv0 = sBias[Fl], bv1 = sBias[Fl + 8];
            float* h0 = g_H + ((size_t)e * FDIM + F) * NTOK;
            float* h1 = h0 + (size_t)8 * NTOK;
            #pragma unroll
            for (int ct = 0; ct < 8; ct++) {
                int m = C0 + C_warp + ct * 8 + 2 * tig;
                float2 v0 = make_float2(gelu_exact(acc[rt][ct][0] + bv0),
                                        gelu_exact(acc[rt][ct][1] + bv0));
                float2 v1 = make_float2(gelu_exact(acc[rt][ct][2] + bv1),
                                        gelu_exact(acc[rt][ct][3] + bv1));
                if (m + 1 < M) {
                    *(float2*)(h0 + m) = v0;
                    *(float2*)(h1 + m) = v1;
                } else if (m < M) {
                    h0[m] = v0.x;
                    h1[m] = v1.x;
                }
            }
        }
    } else {
        const int dl = R_warp + gid;
        #pragma unroll
        for (int ct = 0; ct < 8; ct++) {
            int mA = C0 + C_warp + ct * 8 + 2 * tig;
            #pragma unroll
            for (int j = 0; j < 2; j++) {
                int m = mA + j;
                if (m < M) {
                    int   tok = g_toklist[e * NTOK + m];
                    float wv  = g_tokw[e * NTOK + m];
                    float* o  = out + (size_t)tok * DIM + R0;
                    #pragma unroll
                    for (int rt = 0; rt < 2; rt++) {
                        int d = dl + rt * 16;
                        atomicAdd(&o[d],     wv * (acc[rt][ct][j]     + sBias[d]));
                        atomicAdd(&o[d + 8], wv * (acc[rt][ct][j + 2] + sBias[d + 8]));
                    }
                }
            }
        }
    }
}

// ---------------------------------------------------------------------------
extern "C" void kernel_launch(void* const* d_in, const int* in_sizes, int n_in,
                              void* d_out, int out_size) {
    const float* x    = (const float*)d_in[0];
    const float* Wp   = (const float*)d_in[1];
    const float* sim  = (const float*)d_in[2];
    const float* temp = (const float*)d_in[3];
    const float* W1   = (const float*)d_in[4];
    const float* b1   = (const float*)d_in[5];
    const float* W2   = (const float*)d_in[6];
    const float* b2   = (const float*)d_in[7];
    float* out = (float*)d_out;

    const int smem0 = 512 + 2 * (128 * 36 * 4) + 2 * (128 * 36 * 4);  // 74240
    const int smem1 = 512 + 2 * (32 * 136 * 4) + 2 * (128 * 36 * 4);  // 72192
    const int smem2 = 512 + 2 * (32 * 136 * 4) + 2 * (32 * 136 * 4);  // 70144
    cudaFuncSetAttribute(moe_mma<0>, cudaFuncAttributeMaxDynamicSharedMemorySize, smem0);
    cudaFuncSetAttribute(moe_mma<1>, cudaFuncAttributeMaxDynamicSharedMemorySize, smem1);
    cudaFuncSetAttribute(moe_mma<2>, cudaFuncAttributeMaxDynamicSharedMemorySize, smem2);

    zero_kernel<<<(NTOK * DIM + 255) / 256, 256>>>(out);
    normsim_kernel<<<1, 256>>>(sim);
    gateM_kernel<<<NEXP, 256>>>(Wp);

    dim3 g0(DIM / 128, NTOK / 128, 1);       // (C=n blocks, R=token blocks)
    moe_mma<0><<<g0, 256, smem0>>>(x, Wp, nullptr, nullptr);

    gate2_kernel<<<NTOK / 8, 256>>>(x, temp);
    route_kernel<<<NTOK / 256, 256>>>();

    dim3 g1(FDIM / 128, NTOK / 128, NEXP);   // (R=F blocks, C=token blocks)
    moe_mma<1><<<g1, 256, smem1>>>(x, W1, b1, nullptr);

    dim3 g2(DIM / 128, NTOK / 128, NEXP);    // (R=d blocks, C=token blocks)
    moe_mma<2><<<g2, 256, smem2>>>(x, W2, b2, out);
}

// round 7
// speedup vs baseline: 2.7497x; 1.0010x over previous
#include <cuda_runtime.h>
#include <math.h>
#include <stdint.h>

#define NTOK 4096
#define DIM  1024
#define FDIM 4096
#define NEXP 8

// ---------------- scratch (static device globals; no allocation allowed) ----
__device__ float g_sn[NEXP * DIM];
__device__ float g_M[NEXP * DIM];            // fp32-exact gate numerator matrix
__device__ float g_norm2[NTOK];
__device__ int   g_topi[NTOK * 2];
__device__ float g_topw[NTOK * 2];
__device__ int   g_count[NEXP];
__device__ int   g_toklist[NEXP * NTOK];
__device__ float g_tokw[NEXP * NTOK];
// tf32-rounded copies of the GEMM operands
__device__ float g_xt[(size_t)NTOK * DIM];            // 16 MB
__device__ float g_Wpt[(size_t)DIM * DIM];            // 4 MB
__device__ float g_W1t[(size_t)NEXP * DIM * FDIM];    // 128 MB
__device__ float g_W2t[(size_t)NEXP * FDIM * DIM];    // 128 MB
// H stored TRANSPOSED and tf32-rounded: Ht[e][F][m]
__device__ float g_H[(size_t)NEXP * FDIM * NTOK];     // 512 MB

// ---------------- helpers ---------------------------------------------------
__device__ __forceinline__ uint32_t cvt_tf32(float x) {
    uint32_t r;
    asm("cvt.rna.tf32.f32 %0, %1;" : "=r"(r) : "f"(x));
    return r;
}
__device__ __forceinline__ float cvt_tf32f(float x) {
    return __uint_as_float(cvt_tf32(x));
}
__device__ __forceinline__ uint32_t smem_u32(const void* p) {
    uint32_t a;
    asm("{ .reg .u64 t; cvta.to.shared.u64 t, %1; cvt.u32.u64 %0, t; }" : "=r"(a) : "l"(p));
    return a;
}
__device__ __forceinline__ void cp16(uint32_t dst, const float* src) {
    asm volatile("cp.async.cg.shared.global [%0], [%1], 16;" :: "r"(dst), "l"(src) : "memory");
}
__device__ __forceinline__ void cp_commit() {
    asm volatile("cp.async.commit_group;" ::: "memory");
}
__device__ __forceinline__ void cp_wait1() {
    asm volatile("cp.async.wait_group 1;" ::: "memory");
}
__device__ __forceinline__ void mma_tf32(float* d, const uint32_t* a, const uint32_t* b) {
    asm volatile(
        "mma.sync.aligned.m16n8k8.row.col.f32.tf32.tf32.f32 "
        "{%0,%1,%2,%3}, {%4,%5,%6,%7}, {%8,%9}, {%0,%1,%2,%3};"
        : "+f"(d[0]), "+f"(d[1]), "+f"(d[2]), "+f"(d[3])
        : "r"(a[0]), "r"(a[1]), "r"(a[2]), "r"(a[3]), "r"(b[0]), "r"(b[1]));
}
__device__ __forceinline__ float gelu_exact(float v) {
    return 0.5f * v * (1.0f + erff(v * 0.70710678118654752440f));
}

// ---------------------------------------------------------------------------
__global__ void zero_kernel(float* __restrict__ out) {
    size_t i = (size_t)blockIdx.x * blockDim.x + threadIdx.x;
    if (i < (size_t)NTOK * DIM) out[i] = 0.0f;
    if (i < NTOK) g_norm2[i] = 0.0f;
    if (i < NEXP) g_count[i] = 0;
}

// tf32-round a buffer (float4 granular)
__global__ void cvt_kernel(const float* __restrict__ src, float* __restrict__ dst, int n4) {
    int i = blockIdx.x * blockDim.x + threadIdx.x;
    if (i < n4) {
        float4 v = ((const float4*)src)[i];
        float4 o;
        o.x = cvt_tf32f(v.x); o.y = cvt_tf32f(v.y);
        o.z = cvt_tf32f(v.z); o.w = cvt_tf32f(v.w);
        ((float4*)dst)[i] = o;
    }
}

__global__ void normsim_kernel(const float* __restrict__ sim) {
    int w = threadIdx.x >> 5, lane = threadIdx.x & 31;
    if (w >= NEXP) return;
    float ss = 0.0f;
    for (int k = lane; k < DIM; k += 32) { float v = sim[w * DIM + k]; ss += v * v; }
    #pragma unroll
    for (int off = 16; off; off >>= 1) ss += __shfl_xor_sync(0xffffffffu, ss, off);
    float inv = 1.0f / fmaxf(sqrtf(ss), 1e-12f);
    for (int k = lane; k < DIM; k += 32) g_sn[w * DIM + k] = sim[w * DIM + k] * inv;
}

// M[e][i] = sum_o Wp[o][i] * sn[e][o]   (fp32-exact gate numerators)
__global__ void gateM_kernel(const float* __restrict__ Wp) {
    int e = blockIdx.x;
    int i0 = threadIdx.x * 4;
    float4 acc = make_float4(0, 0, 0, 0);
    #pragma unroll 4
    for (int o = 0; o < DIM; o++) {
        float s = g_sn[e * DIM + o];
        float4 w = *(const float4*)(Wp + (size_t)o * DIM + i0);
        acc.x += s * w.x; acc.y += s * w.y; acc.z += s * w.z; acc.w += s * w.w;
    }
    *(float4*)(g_M + e * DIM + i0) = acc;
}

// one warp per token: fp32 dots x.M_e; |p| from tf32 norm; top2+softmax
__global__ void gate2_kernel(const float* __restrict__ x, const float* __restrict__ temp) {
    __shared__ float sM[NEXP][DIM];
    int tid = threadIdx.x;
    for (int i = tid; i < NEXP * DIM; i += 256) ((float*)sM)[i] = g_M[i];
    __syncthreads();
    int w = tid >> 5, lane = tid & 31;
    int t = blockIdx.x * 8 + w;
    const float4* xr = (const float4*)(x + (size_t)t * DIM);
    float acc[NEXP];
    #pragma unroll
    for (int e = 0; e < NEXP; e++) acc[e] = 0.0f;
    for (int k4 = lane; k4 < DIM / 4; k4 += 32) {
        float4 xv = xr[k4];
        #pragma unroll
        for (int e = 0; e < NEXP; e++) {
            float4 mv = *(const float4*)&sM[e][k4 * 4];
            acc[e] += xv.x * mv.x + xv.y * mv.y + xv.z * mv.z + xv.w * mv.w;
        }
    }
    #pragma unroll
    for (int off = 16; off; off >>= 1)
        #pragma unroll
        for (int e = 0; e < NEXP; e++) acc[e] += __shfl_xor_sync(0xffffffffu, acc[e], off);
    if (lane == 0) {
        float pn   = sqrtf(g_norm2[t]);
        float inv  = 1.0f / fmaxf(pn, 1e-12f);
        float tinv = 1.0f / temp[0];
        float sc[NEXP];
        #pragma unroll
        for (int e = 0; e < NEXP; e++) sc[e] = acc[e] * inv * tinv;
        int i0 = 0; float v0 = sc[0];
        #pragma unroll
        for (int e = 1; e < NEXP; e++) if (sc[e] > v0) { v0 = sc[e]; i0 = e; }
        int i1 = -1; float v1 = -1e30f;
        #pragma unroll
        for (int e = 0; e < NEXP; e++) if (e != i0 && sc[e] > v1) { v1 = sc[e]; i1 = e; }
        float e1 = expf(v1 - v0);
        float w0 = 1.0f / (1.0f + e1);
        g_topi[t * 2] = i0;  g_topi[t * 2 + 1] = i1;
        g_topw[t * 2] = w0;  g_topw[t * 2 + 1] = e1 * w0;
    }
}

__global__ void route_kernel() {
    int t = blockIdx.x * blockDim.x + threadIdx.x;
    if (t >= NTOK) return;
    #pragma unroll
    for (int k = 0; k < 2; k++) {
        int e = g_topi[t * 2 + k];
        int pos = atomicAdd(&g_count[e], 1);
        g_toklist[e * NTOK + pos] = t;
        g_tokw[e * NTOK + pos]    = g_topw[t * 2 + k];
    }
}

// ---------------------------------------------------------------------------
// tf32 mma.sync GEMM, tile 128(R) x 128(C) x 32, 8 warps (4R x 2C).
// cp.async 3-stage pipeline; operands pre-converted to tf32 (no cvt in loop).
// MODE 0: R=tokens, C=proj-features. A=xt[m][k], B=Wpt[n][k].
// MODE 1: R=F, C=tokens. A=W1t[k][F], B=xt[gather m][k]. -> Ht (tf32-rounded)
// MODE 2: R=d, C=tokens. A=W2t[k][d], B=Ht[e][k=F][m].   -> out (atomicAdd)
// ---------------------------------------------------------------------------
template<int MODE>
__global__ __launch_bounds__(256, 2)
void moe_mma(const float* __restrict__ Abase, const float* __restrict__ Bbase,
             const float* __restrict__ bias, float* __restrict__ out) {
    constexpr int K    = (MODE == 2) ? FDIM : DIM;
    constexpr int ND   = (MODE == 1) ? FDIM : DIM;
    constexpr bool AKC = (MODE != 0);      // A tile [k][r] stride 136
    constexpr bool BKC = (MODE == 2);      // B tile [k][c] stride 136
    constexpr int A_SZ = AKC ? 32 * 136 : 128 * 36;   // floats per stage
    constexpr int B_SZ = BKC ? 32 * 136 : 128 * 36;
    constexpr int STAGE = A_SZ + B_SZ;
    constexpr int STG = 3;

    extern __shared__ float sm[];
    float* sBias = sm;                      // 128 floats (512 B)
    const uint32_t smb = smem_u32(sm);

    const int tid  = threadIdx.x;
    const int lane = tid & 31;
    const int wid  = tid >> 5;
    const int gid  = lane >> 2;
    const int tig  = lane & 3;
    const int R_warp = (wid & 3) * 32;
    const int C_warp = (wid >> 2) * 64;
    const int e  = blockIdx.z;

    const int R0 = (MODE == 0 ? blockIdx.y : blockIdx.x) * 128;
    const int C0 = (MODE == 0 ? blockIdx.x : blockIdx.y) * 128;
    int M = NTOK;
    const int* rows = nullptr;
    const float* We = Abase;
    if (MODE != 0) {
        M = g_count[e];
        if (C0 >= M) return;
        rows = g_toklist + e * NTOK;
        We = Abase + (size_t)e * K * ND;
    }
    if (MODE != 0 && tid < 128)
        sBias[tid] = bias[(size_t)e * ND + R0 + tid];

    // ---- per-thread copy geometry ----
    const float* aSrc;
    uint32_t aOff;
    size_t aKStep, aStep;
    uint32_t aDstStep;
    if (MODE == 0) {
        int arow = tid >> 1, ah = (tid & 1) * 16;
        aSrc = Abase + (size_t)(R0 + arow) * DIM + ah;
        aKStep = 32; aStep = 4;
        aOff = arow * 36 + ah; aDstStep = 4;
    } else {
        int kr = tid >> 5, nq = (tid & 31) * 4;
        aSrc = We + (size_t)kr * ND + R0 + nq;
        aKStep = (size_t)32 * ND; aStep = (size_t)8 * ND;
        aOff = kr * 136 + nq; aDstStep = 8 * 136;
    }
    const float* bSrc;
    uint32_t bOff;
    size_t bKStep, bStep;
    uint32_t bDstStep;
    if (MODE == 0) {
        int brow = tid >> 1, bh = (tid & 1) * 16;
        bSrc = Bbase + (size_t)(C0 + brow) * DIM + bh;
        bKStep = 32; bStep = 4;
        bOff = brow * 36 + bh; bDstStep = 4;
    } else if (MODE == 1) {
        int brow = tid >> 1, bh = (tid & 1) * 16;
        int gm = C0 + brow;
        int gr = (gm < M) ? rows[gm] : 0;
        bSrc = Bbase + (size_t)gr * DIM + bh;
        bKStep = 32; bStep = 4;
        bOff = brow * 36 + bh; bDstStep = 4;
    } else {
        int fr = tid >> 5, mq = (tid & 31) * 4;
        bSrc = Bbase + ((size_t)e * FDIM + fr) * NTOK + C0 + mq;
        bKStep = (size_t)32 * NTOK; bStep = (size_t)8 * NTOK;
        bOff = fr * 136 + mq; bDstStep = 8 * 136;
    }

    auto issue = [&](int c, int s) {
        uint32_t aD = smb + 512 + (uint32_t)(s * STAGE) * 4 + aOff * 4;
        uint32_t bD = aD - aOff * 4 + (uint32_t)A_SZ * 4 + bOff * 4;
        const float* aS = aSrc + (size_t)c * aKStep;
        const float* bS = bSrc + (size_t)c * bKStep;
        #pragma unroll
        for (int i = 0; i < 4; i++) cp16(aD + i * aDstStep * 4, aS + i * aStep);
        #pragma unroll
        for (int i = 0; i < 4; i++) cp16(bD + i * bDstStep * 4, bS + i * bStep);
    };

    float acc[2][8][4];
    #pragma unroll
    for (int i = 0; i < 2; i++)
        #pragma unroll
        for (int j = 0; j < 8; j++)
            #pragma unroll
            for (int q = 0; q < 4; q++) acc[i][j][q] = 0.0f;

    constexpr int nch = K / 32;
    issue(0, 0); cp_commit();
    issue(1, 1); cp_commit();

    for (int c = 0; c < nch; ++c) {
        cp_wait1();
        __syncthreads();
        if (c + STG - 1 < nch) issue(c + STG - 1, (c + STG - 1) % STG);
        cp_commit();

        const uint32_t* sA = (const uint32_t*)(sm + 128 + (c % STG) * STAGE);
        const uint32_t* sB = sA + A_SZ;
        #pragma unroll
        for (int kb = 0; kb < 4; kb++) {
            const int k = kb * 8 + tig;
            uint32_t af[2][4];
            #pragma unroll
            for (int rt = 0; rt < 2; rt++) {
                const int r = R_warp + rt * 16 + gid;
                if (AKC) {
                    af[rt][0] = sA[k * 136 + r];       af[rt][1] = sA[k * 136 + r + 8];
                    af[rt][2] = sA[(k + 4) * 136 + r]; af[rt][3] = sA[(k + 4) * 136 + r + 8];
                } else {
                    af[rt][0] = sA[r * 36 + k];        af[rt][1] = sA[(r + 8) * 36 + k];
                    af[rt][2] = sA[r * 36 + k + 4];    af[rt][3] = sA[(r + 8) * 36 + k + 4];
                }
            }
            #pragma unroll
            for (int ct = 0; ct < 8; ct++) {
                const int cc = C_warp + ct * 8 + gid;
                uint32_t bf[2];
                if (BKC) { bf[0] = sB[k * 136 + cc]; bf[1] = sB[(k + 4) * 136 + cc]; }
                else     { bf[0] = sB[cc * 36 + k];  bf[1] = sB[cc * 36 + k + 4];  }
                mma_tf32(acc[0][ct], af[0], bf);
                mma_tf32(acc[1][ct], af[1], bf);
            }
        }
        __syncthreads();
    }

    // ---- epilogue ----
    if (MODE == 0) {
        #pragma unroll
        for (int rt = 0; rt < 2; rt++) {
            float s0 = 0.0f, s1 = 0.0f;
            #pragma unroll
            for (int ct = 0; ct < 8; ct++) {
                s0 += acc[rt][ct][0] * acc[rt][ct][0] + acc[rt][ct][1] * acc[rt][ct][1];
                s1 += acc[rt][ct][2] * acc[rt][ct][2] + acc[rt][ct][3] * acc[rt][ct][3];
            }
            s0 += __shfl_xor_sync(0xffffffffu, s0, 1);
            s0 += __shfl_xor_sync(0xffffffffu, s0, 2);
            s1 += __shfl_xor_sync(0xffffffffu, s1, 1);
            s1 += __shfl_xor_sync(0xffffffffu, s1, 2);
            if (tig == 0) {
                int r = R0 + R_warp + rt * 16 + gid;
                atomicAdd(&g_norm2[r], s0);
                atomicAdd(&g_norm2[r + 8], s1);
            }
        }
    } else if (MODE == 1) {
        #pragma unroll
        for (int rt = 0; rt < 2; rt++) {
            const int Fl = R_warp + rt * 16 + gid;
            const int F  = R0 + Fl;
            const float bv0 = sBias[Fl], bv1 = sBias[Fl + 8];
            float* h0 = g_H + ((size_t)e * FDIM + F) * NTOK;
            float* h1 = h0 + (size_t)8 * NTOK;
            #pragma unroll
            for (int ct = 0; ct < 8; ct++) {
                int m = C0 + C_warp + ct * 8 + 2 * tig;
                float2 v0 = make_float2(cvt_tf32f(gelu_exact(acc[rt][ct][0] + bv0)),
                                        cvt_tf32f(gelu_exact(acc[rt][ct][1] + bv0)));
                float2 v1 = make_float2(cvt_tf32f(gelu_exact(acc[rt][ct][2] + bv1)),
                                        cvt_tf32f(gelu_exact(acc[rt][ct][3] + bv1)));
                if (m + 1 < M) {
                    *(float2*)(h0 + m) = v0;
                    *(float2*)(h1 + m) = v1;
                } else if (m < M) {
                    h0[m] = v0.x;
                    h1[m] = v1.x;
                }
            }
        }
    } else {
        const int dl = R_warp + gid;
        #pragma unroll
        for (int ct = 0; ct < 8; ct++) {
            int mA = C0 + C_warp + ct * 8 + 2 * tig;
            #pragma unroll
            for (int j = 0; j < 2; j++) {
                int m = mA + j;
                if (m < M) {
                    int   tok = g_toklist[e * NTOK + m];
                    float wv  = g_tokw[e * NTOK + m];
                    float* o  = out + (size_t)tok * DIM + R0;
                    #pragma unroll
                    for (int rt = 0; rt < 2; rt++) {
                        int d = dl + rt * 16;
                        atomicAdd(&o[d],     wv * (acc[rt][ct][j]     + sBias[d]));
                        atomicAdd(&o[d + 8], wv * (acc[rt][ct][j + 2] + sBias[d + 8]));
                    }
                }
            }
        }
    }
}

// ---------------------------------------------------------------------------
extern "C" void kernel_launch(void* const* d_in, const int* in_sizes, int n_in,
                              void* d_out, int out_size) {
    const float* x    = (const float*)d_in[0];
    const float* Wp   = (const float*)d_in[1];
    const float* sim  = (const float*)d_in[2];
    const float* temp = (const float*)d_in[3];
    const float* W1   = (const float*)d_in[4];
    const float* b1   = (const float*)d_in[5];
    const float* W2   = (const float*)d_in[6];
    const float* b2   = (const float*)d_in[7];
    float* out = (float*)d_out;

    const int smem0 = 512 + 3 * (128 * 36 + 128 * 36) * 4;  // 111104
    const int smem1 = 512 + 3 * (32 * 136 + 128 * 36) * 4;  // 108032
    const int smem2 = 512 + 3 * (32 * 136 + 32 * 136) * 4;  // 104960
    cudaFuncSetAttribute(moe_mma<0>, cudaFuncAttributeMaxDynamicSharedMemorySize, smem0);
    cudaFuncSetAttribute(moe_mma<1>, cudaFuncAttributeMaxDynamicSharedMemorySize, smem1);
    cudaFuncSetAttribute(moe_mma<2>, cudaFuncAttributeMaxDynamicSharedMemorySize, smem2);

    zero_kernel<<<(NTOK * DIM + 255) / 256, 256>>>(out);
    normsim_kernel<<<1, 256>>>(sim);
    gateM_kernel<<<NEXP, 256>>>(Wp);

    // tf32-round operands once
    float* d_xt;  cudaGetSymbolAddress((void**)&d_xt,  g_xt);
    float* d_wpt; cudaGetSymbolAddress((void**)&d_wpt, g_Wpt);
    float* d_w1t; cudaGetSymbolAddress((void**)&d_w1t, g_W1t);
    float* d_w2t; cudaGetSymbolAddress((void**)&d_w2t, g_W2t);
    float* d_H;   cudaGetSymbolAddress((void**)&d_H,   g_H);
    cvt_kernel<<<(NTOK * DIM / 4 + 255) / 256, 256>>>(x, d_xt, NTOK * DIM / 4);
    cvt_kernel<<<(DIM * DIM / 4 + 255) / 256, 256>>>(Wp, d_wpt, DIM * DIM / 4);
    cvt_kernel<<<(NEXP * DIM * FDIM / 4 + 255) / 256, 256>>>(W1, d_w1t, NEXP * DIM * FDIM / 4);
    cvt_kernel<<<(NEXP * FDIM * DIM / 4 + 255) / 256, 256>>>(W2, d_w2t, NEXP * FDIM * DIM / 4);

    dim3 g0(DIM / 128, NTOK / 128, 1);
    moe_mma<0><<<g0, 256, smem0>>>(d_xt, d_wpt, nullptr, nullptr);

    gate2_kernel<<<NTOK / 8, 256>>>(x, temp);
    route_kernel<<<NTOK / 256, 256>>>();

    dim3 g1(FDIM / 128, NTOK / 128, NEXP);
    moe_mma<1><<<g1, 256, smem1>>>(d_w1t, d_xt, b1, nullptr);

    dim3 g2(DIM / 128, NTOK / 128, NEXP);
    moe_mma<2><<<g2, 256, smem2>>>(d_w2t, d_H, b2, out);
}

// round 9
// speedup vs baseline: 2.8349x; 1.0310x over previous
#include <cuda_runtime.h>
#include <math.h>
#include <stdint.h>

#define NTOK 4096
#define DIM  1024
#define FDIM 4096
#define NEXP 8

// ---------------- scratch (static device globals; no allocation allowed) ----
__device__ float g_sn[NEXP * DIM];
__device__ float g_M[NEXP * DIM];            // fp32-exact gate numerator matrix
__device__ float g_norm2[NTOK];
__device__ int   g_topi[NTOK * 2];
__device__ float g_topw[NTOK * 2];
__device__ int   g_count[NEXP];
__device__ int   g_toklist[NEXP * NTOK];
__device__ float g_tokw[NEXP * NTOK];
// tf32-rounded copies of the GEMM operands
__device__ float g_xt[(size_t)NTOK * DIM];            // 16 MB
__device__ float g_Wpt[(size_t)DIM * DIM];            // 4 MB
__device__ float g_W1t[(size_t)NEXP * DIM * FDIM];    // 128 MB
__device__ float g_W2t[(size_t)NEXP * FDIM * DIM];    // 128 MB
// H stored TRANSPOSED and tf32-rounded: Ht[e][F][m]
__device__ float g_H[(size_t)NEXP * FDIM * NTOK];     // 512 MB

// ---------------- helpers ---------------------------------------------------
__device__ __forceinline__ uint32_t cvt_tf32(float x) {
    uint32_t r;
    asm("cvt.rna.tf32.f32 %0, %1;" : "=r"(r) : "f"(x));
    return r;
}
__device__ __forceinline__ float cvt_tf32f(float x) {
    return __uint_as_float(cvt_tf32(x));
}
__device__ __forceinline__ uint32_t smem_u32(const void* p) {
    uint32_t a;
    asm("{ .reg .u64 t; cvta.to.shared.u64 t, %1; cvt.u32.u64 %0, t; }" : "=r"(a) : "l"(p));
    return a;
}
__device__ __forceinline__ void cp16(uint32_t dst, const float* src) {
    asm volatile("cp.async.cg.shared.global [%0], [%1], 16;" :: "r"(dst), "l"(src) : "memory");
}
__device__ __forceinline__ void cp_commit() {
    asm volatile("cp.async.commit_group;" ::: "memory");
}
__device__ __forceinline__ void cp_wait1() {
    asm volatile("cp.async.wait_group 1;" ::: "memory");
}
__device__ __forceinline__ void mma_tf32(float* d, const uint32_t* a, const uint32_t* b) {
    asm volatile(
        "mma.sync.aligned.m16n8k8.row.col.f32.tf32.tf32.f32 "
        "{%0,%1,%2,%3}, {%4,%5,%6,%7}, {%8,%9}, {%0,%1,%2,%3};"
        : "+f"(d[0]), "+f"(d[1]), "+f"(d[2]), "+f"(d[3])
        : "r"(a[0]), "r"(a[1]), "r"(a[2]), "r"(a[3]), "r"(b[0]), "r"(b[1]));
}
__device__ __forceinline__ float gelu_exact(float v) {
    return 0.5f * v * (1.0f + erff(v * 0.70710678118654752440f));
}

// ---------------------------------------------------------------------------
__global__ void zero_kernel(float* __restrict__ out) {
    size_t i = (size_t)blockIdx.x * blockDim.x + threadIdx.x;
    if (i < (size_t)NTOK * DIM) out[i] = 0.0f;
    if (i < NTOK) g_norm2[i] = 0.0f;
    if (i < NEXP) g_count[i] = 0;
}

// tf32-round a buffer (float4 granular)
__global__ void cvt_kernel(const float* __restrict__ src, float* __restrict__ dst, int n4) {
    int i = blockIdx.x * blockDim.x + threadIdx.x;
    if (i < n4) {
        float4 v = ((const float4*)src)[i];
        float4 o;
        o.x = cvt_tf32f(v.x); o.y = cvt_tf32f(v.y);
        o.z = cvt_tf32f(v.z); o.w = cvt_tf32f(v.w);
        ((float4*)dst)[i] = o;
    }
}

__global__ void normsim_kernel(const float* __restrict__ sim) {
    int w = threadIdx.x >> 5, lane = threadIdx.x & 31;
    if (w >= NEXP) return;
    float ss = 0.0f;
    for (int k = lane; k < DIM; k += 32) { float v = sim[w * DIM + k]; ss += v * v; }
    #pragma unroll
    for (int off = 16; off; off >>= 1) ss += __shfl_xor_sync(0xffffffffu, ss, off);
    float inv = 1.0f / fmaxf(sqrtf(ss), 1e-12f);
    for (int k = lane; k < DIM; k += 32) g_sn[w * DIM + k] = sim[w * DIM + k] * inv;
}

// M[e][i] = sum_o Wp[o][i] * sn[e][o]   (fp32-exact gate numerators)
__global__ void gateM_kernel(const float* __restrict__ Wp) {
    int e = blockIdx.x;
    int i0 = threadIdx.x * 4;
    float4 acc = make_float4(0, 0, 0, 0);
    #pragma unroll 4
    for (int o = 0; o < DIM; o++) {
        float s = g_sn[e * DIM + o];
        float4 w = *(const float4*)(Wp + (size_t)o * DIM + i0);
        acc.x += s * w.x; acc.y += s * w.y; acc.z += s * w.z; acc.w += s * w.w;
    }
    *(float4*)(g_M + e * DIM + i0) = acc;
}

// one warp per token: fp32 dots x.M_e; |p| from tf32 norm; top2+softmax
__global__ void gate2_kernel(const float* __restrict__ x, const float* __restrict__ temp) {
    __shared__ float sM[NEXP][DIM];
    int tid = threadIdx.x;
    for (int i = tid; i < NEXP * DIM; i += 256) ((float*)sM)[i] = g_M[i];
    __syncthreads();
    int w = tid >> 5, lane = tid & 31;
    int t = blockIdx.x * 8 + w;
    const float4* xr = (const float4*)(x + (size_t)t * DIM);
    float acc[NEXP];
    #pragma unroll
    for (int e = 0; e < NEXP; e++) acc[e] = 0.0f;
    for (int k4 = lane; k4 < DIM / 4; k4 += 32) {
        float4 xv = xr[k4];
        #pragma unroll
        for (int e = 0; e < NEXP; e++) {
            float4 mv = *(const float4*)&sM[e][k4 * 4];
            acc[e] += xv.x * mv.x + xv.y * mv.y + xv.z * mv.z + xv.w * mv.w;
        }
    }
    #pragma unroll
    for (int off = 16; off; off >>= 1)
        #pragma unroll
        for (int e = 0; e < NEXP; e++) acc[e] += __shfl_xor_sync(0xffffffffu, acc[e], off);
    if (lane == 0) {
        float pn   = sqrtf(g_norm2[t]);
        float inv  = 1.0f / fmaxf(pn, 1e-12f);
        float tinv = 1.0f / temp[0];
        float sc[NEXP];
        #pragma unroll
        for (int e = 0; e < NEXP; e++) sc[e] = acc[e] * inv * tinv;
        int i0 = 0; float v0 = sc[0];
        #pragma unroll
        for (int e = 1; e < NEXP; e++) if (sc[e] > v0) { v0 = sc[e]; i0 = e; }
        int i1 = -1; float v1 = -1e30f;
        #pragma unroll
        for (int e = 0; e < NEXP; e++) if (e != i0 && sc[e] > v1) { v1 = sc[e]; i1 = e; }
        float e1 = expf(v1 - v0);
        float w0 = 1.0f / (1.0f + e1);
        g_topi[t * 2] = i0;  g_topi[t * 2 + 1] = i1;
        g_topw[t * 2] = w0;  g_topw[t * 2 + 1] = e1 * w0;
    }
}

__global__ void route_kernel() {
    int t = blockIdx.x * blockDim.x + threadIdx.x;
    if (t >= NTOK) return;
    #pragma unroll
    for (int k = 0; k < 2; k++) {
        int e = g_topi[t * 2 + k];
        int pos = atomicAdd(&g_count[e], 1);
        g_toklist[e * NTOK + pos] = t;
        g_tokw[e * NTOK + pos]    = g_topw[t * 2 + k];
    }
}

// ---------------------------------------------------------------------------
// tf32 mma.sync GEMM, CTA tile 256(R) x 128(C) x 32, 8 warps (4R x 2C),
// warp tile 64x64, cp.async 3-stage ring, ONE sync per chunk.
// MODE 0: R=tokens, C=proj-features. A=xt[m][k], B=Wpt[n][k].
// MODE 1: R=F, C=tokens. A=W1t[k][F], B=xt[gather m][k]. -> Ht (tf32-rounded)
// MODE 2: R=d, C=tokens. A=W2t[k][d], B=Ht[e][k=F][m].   -> out (atomicAdd)
// ---------------------------------------------------------------------------
template<int MODE>
__global__ __launch_bounds__(256)
void moe_mma(const float* __restrict__ Abase, const float* __restrict__ Bbase,
             const float* __restrict__ bias, float* __restrict__ out) {
    constexpr int K    = (MODE == 2) ? FDIM : DIM;
    constexpr int ND   = (MODE == 1) ? FDIM : DIM;
    constexpr bool AKC = (MODE != 0);      // A tile [k][r] stride 264
    constexpr bool BKC = (MODE == 2);      // B tile [k][c] stride 136
    constexpr int A_SZ = AKC ? 32 * 264 : 256 * 36;   // floats per stage
    constexpr int B_SZ = BKC ? 32 * 136 : 128 * 36;
    constexpr int STAGE = A_SZ + B_SZ;
    constexpr int STG = 3;

    extern __shared__ float sm[];
    float* sBias = sm;                      // 256 floats (1024 B)
    const uint32_t smb = smem_u32(sm);

    const int tid  = threadIdx.x;
    const int lane = tid & 31;
    const int wid  = tid >> 5;
    const int gid  = lane >> 2;
    const int tig  = lane & 3;
    const int R_warp = (wid & 3) * 64;
    const int C_warp = (wid >> 2) * 64;
    const int e  = blockIdx.z;

    const int R0 = (MODE == 0 ? blockIdx.y : blockIdx.x) * 256;
    const int C0 = (MODE == 0 ? blockIdx.x : blockIdx.y) * 128;
    int M = NTOK;
    const int* rows = nullptr;
    const float* We = Abase;
    if (MODE != 0) {
        M = g_count[e];
        if (C0 >= M) return;
        rows = g_toklist + e * NTOK;
        We = Abase + (size_t)e * K * ND;
    }
    if (MODE != 0)
        sBias[tid] = bias[(size_t)e * ND + R0 + tid];

    // ---- per-thread copy geometry: A = 8 cp16, B = 4 cp16 per chunk ----
    const float* aSrc;
    uint32_t aOff;            // float offset within A stage
    size_t aKStep, aStep;     // src advance per chunk / per copy i
    uint32_t aDstStep;        // smem float advance per copy i
    if (MODE == 0) {
        int row = tid >> 3, koff = (tid & 7) * 4;     // 32 rows/pass, 8 passes
        aSrc = Abase + (size_t)(R0 + row) * DIM + koff;
        aKStep = 32; aStep = (size_t)32 * DIM;
        aOff = row * 36 + koff; aDstStep = 32 * 36;
    } else {
        int ka = tid >> 6, roff = (tid & 63) * 4;     // 4 k/pass, 8 passes
        aSrc = We + (size_t)ka * ND + R0 + roff;
        aKStep = (size_t)32 * ND; aStep = (size_t)4 * ND;
        aOff = ka * 264 + roff; aDstStep = 4 * 264;
    }
    const float* bSrc;
    uint32_t bOff;
    size_t bKStep, bStep;
    uint32_t bDstStep;
    if (MODE == 0) {
        int brow = tid >> 1, bh = (tid & 1) * 16;
        bSrc = Bbase + (size_t)(C0 + brow) * DIM + bh;
        bKStep = 32; bStep = 4;
        bOff = brow * 36 + bh; bDstStep = 4;
    } else if (MODE == 1) {
        int brow = tid >> 1, bh = (tid & 1) * 16;
        int gm = C0 + brow;
        int gr = (gm < M) ? rows[gm] : 0;
        bSrc = Bbase + (size_t)gr * DIM + bh;
        bKStep = 32; bStep = 4;
        bOff = brow * 36 + bh; bDstStep = 4;
    } else {
        int fr = tid >> 5, mq = (tid & 31) * 4;
        bSrc = Bbase + ((size_t)e * FDIM + fr) * NTOK + C0 + mq;
        bKStep = (size_t)32 * NTOK; bStep = (size_t)8 * NTOK;
        bOff = fr * 136 + mq; bDstStep = 8 * 136;
    }

    auto issue = [&](int c, int s) {
        uint32_t aD = smb + 1024 + (uint32_t)(s * STAGE) * 4 + aOff * 4;
        uint32_t bD = smb + 1024 + (uint32_t)(s * STAGE) * 4 + (uint32_t)A_SZ * 4 + bOff * 4;
        const float* aS = aSrc + (size_t)c * aKStep;
        const float* bS = bSrc + (size_t)c * bKStep;
        #pragma unroll
        for (int i = 0; i < 8; i++) cp16(aD + i * aDstStep * 4, aS + i * aStep);
        #pragma unroll
        for (int i = 0; i < 4; i++) cp16(bD + i * bDstStep * 4, bS + i * bStep);
    };

    float acc[4][8][4];
    #pragma unroll
    for (int i = 0; i < 4; i++)
        #pragma unroll
        for (int j = 0; j < 8; j++)
            #pragma unroll
            for (int q = 0; q < 4; q++) acc[i][j][q] = 0.0f;

    constexpr int nch = K / 32;
    issue(0, 0); cp_commit();
    issue(1, 1); cp_commit();

    for (int c = 0; c < nch; ++c) {
        cp_wait1();
        __syncthreads();
        if (c + 2 < nch) issue(c + 2, (c + 2) % STG);
        cp_commit();

        const uint32_t* sA = (const uint32_t*)(sm + 256 + (c % STG) * STAGE);
        const uint32_t* sB = sA + A_SZ;
        #pragma unroll
        for (int kb = 0; kb < 4; kb++) {
            const int k = kb * 8 + tig;
            uint32_t af[4][4];
            #pragma unroll
            for (int rt = 0; rt < 4; rt++) {
                const int r = R_warp + rt * 16 + gid;
                if (AKC) {
                    af[rt][0] = sA[k * 264 + r];       af[rt][1] = sA[k * 264 + r + 8];
                    af[rt][2] = sA[(k + 4) * 264 + r]; af[rt][3] = sA[(k + 4) * 264 + r + 8];
                } else {
                    af[rt][0] = sA[r * 36 + k];        af[rt][1] = sA[(r + 8) * 36 + k];
                    af[rt][2] = sA[r * 36 + k + 4];    af[rt][3] = sA[(r + 8) * 36 + k + 4];
                }
            }
            #pragma unroll
            for (int ct = 0; ct < 8; ct++) {
                const int cc = C_warp + ct * 8 + gid;
                uint32_t bf[2];
                if (BKC) { bf[0] = sB[k * 136 + cc]; bf[1] = sB[(k + 4) * 136 + cc]; }
                else     { bf[0] = sB[cc * 36 + k];  bf[1] = sB[cc * 36 + k + 4];  }
                #pragma unroll
                for (int rt = 0; rt < 4; rt++)
                    mma_tf32(acc[rt][ct], af[rt], bf);
            }
        }
        // no bottom sync: next iteration's top sync orders ring reuse
    }

    // ---- epilogue ----
    if (MODE == 0) {
        #pragma unroll
        for (int rt = 0; rt < 4; rt++) {
            float s0 = 0.0f, s1 = 0.0f;
            #pragma unroll
            for (int ct = 0; ct < 8; ct++) {
                s0 += acc[rt][ct][0] * acc[rt][ct][0] + acc[rt][ct][1] * acc[rt][ct][1];
                s1 += acc[rt][ct][2] * acc[rt][ct][2] + acc[rt][ct][3] * acc[rt][ct][3];
            }
            s0 += __shfl_xor_sync(0xffffffffu, s0, 1);
            s0 += __shfl_xor_sync(0xffffffffu, s0, 2);
            s1 += __shfl_xor_sync(0xffffffffu, s1, 1);
            s1 += __shfl_xor_sync(0xffffffffu, s1, 2);
            if (tig == 0) {
                int r = R0 + R_warp + rt * 16 + gid;
                atomicAdd(&g_norm2[r], s0);
                atomicAdd(&g_norm2[r + 8], s1);
            }
        }
    } else if (MODE == 1) {
        #pragma unroll
        for (int rt = 0; rt < 4; rt++) {
            const int Fl = R_warp + rt * 16 + gid;
            const int F  = R0 + Fl;
            const float bv0 = sBias[Fl], bv1 = sBias[Fl + 8];
            float* h0 = g_H + ((size_t)e * FDIM + F) * NTOK;
            float* h1 = h0 + (size_t)8 * NTOK;
            #pragma unroll
            for (int ct = 0; ct < 8; ct++) {
                int m = C0 + C_warp + ct * 8 + 2 * tig;
                float2 v0 = make_float2(cvt_tf32f(gelu_exact(acc[rt][ct][0] + bv0)),
                                        cvt_tf32f(gelu_exact(acc[rt][ct][1] + bv0)));
                float2 v1 = make_float2(cvt_tf32f(gelu_exact(acc[rt][ct][2] + bv1)),
                                        cvt_tf32f(gelu_exact(acc[rt][ct][3] + bv1)));
                if (m + 1 < M) {
                    *(float2*)(h0 + m) = v0;
                    *(float2*)(h1 + m) = v1;
                } else if (m < M) {
                    h0[m] = v0.x;
                    h1[m] = v1.x;
                }
            }
        }
    } else {
        #pragma unroll
        for (int ct = 0; ct < 8; ct++) {
            int mA = C0 + C_warp + ct * 8 + 2 * tig;
            #pragma unroll
            for (int j = 0; j < 2; j++) {
                int m = mA + j;
                if (m < M) {
                    int   tok = g_toklist[e * NTOK + m];
                    float wv  = g_tokw[e * NTOK + m];
                    float* o  = out + (size_t)tok * DIM + R0;
                    #pragma unroll
                    for (int rt = 0; rt < 4; rt++) {
                        int d = R_warp + rt * 16 + gid;
                        atomicAdd(&o[d],     wv * (acc[rt][ct][j]     + sBias[d]));
                        atomicAdd(&o[d + 8], wv * (acc[rt][ct][j + 2] + sBias[d + 8]));
                    }
                }
            }
        }
    }
}

// ---------------------------------------------------------------------------
extern "C" void kernel_launch(void* const* d_in, const int* in_sizes, int n_in,
                              void* d_out, int out_size) {
    const float* x    = (const float*)d_in[0];
    const float* Wp   = (const float*)d_in[1];
    const float* sim  = (const float*)d_in[2];
    const float* temp = (const float*)d_in[3];
    const float* W1   = (const float*)d_in[4];
    const float* b1   = (const float*)d_in[5];
    const float* W2   = (const float*)d_in[6];
    const float* b2   = (const float*)d_in[7];
    float* out = (float*)d_out;

    const int smem0 = 1024 + 3 * (256 * 36 + 128 * 36) * 4;  // 166912
    const int smem1 = 1024 + 3 * (32 * 264 + 128 * 36) * 4;  // 157696
    const int smem2 = 1024 + 3 * (32 * 264 + 32 * 136) * 4;  // 154624
    cudaFuncSetAttribute(moe_mma<0>, cudaFuncAttributeMaxDynamicSharedMemorySize, smem0);
    cudaFuncSetAttribute(moe_mma<1>, cudaFuncAttributeMaxDynamicSharedMemorySize, smem1);
    cudaFuncSetAttribute(moe_mma<2>, cudaFuncAttributeMaxDynamicSharedMemorySize, smem2);

    zero_kernel<<<(NTOK * DIM + 255) / 256, 256>>>(out);
    normsim_kernel<<<1, 256>>>(sim);
    gateM_kernel<<<NEXP, 256>>>(Wp);

    // tf32-round operands once
    float* d_xt;  cudaGetSymbolAddress((void**)&d_xt,  g_xt);
    float* d_wpt; cudaGetSymbolAddress((void**)&d_wpt, g_Wpt);
    float* d_w1t; cudaGetSymbolAddress((void**)&d_w1t, g_W1t);
    float* d_w2t; cudaGetSymbolAddress((void**)&d_w2t, g_W2t);
    float* d_H;   cudaGetSymbolAddress((void**)&d_H,   g_H);
    cvt_kernel<<<(NTOK * DIM / 4 + 255) / 256, 256>>>(x, d_xt, NTOK * DIM / 4);
    cvt_kernel<<<(DIM * DIM / 4 + 255) / 256, 256>>>(Wp, d_wpt, DIM * DIM / 4);
    cvt_kernel<<<(NEXP * DIM * FDIM / 4 + 255) / 256, 256>>>(W1, d_w1t, NEXP * DIM * FDIM / 4);
    cvt_kernel<<<(NEXP * FDIM * DIM / 4 + 255) / 256, 256>>>(W2, d_w2t, NEXP * FDIM * DIM / 4);

    dim3 g0(DIM / 128, NTOK / 256, 1);          // C-blocks x R-blocks
    moe_mma<0><<<g0, 256, smem0>>>(d_xt, d_wpt, nullptr, nullptr);

    gate2_kernel<<<NTOK / 8, 256>>>(x, temp);
    route_kernel<<<NTOK / 256, 256>>>();

    dim3 g1(FDIM / 256, NTOK / 128, NEXP);      // R-blocks x C-blocks x E
    moe_mma<1><<<g1, 256, smem1>>>(d_w1t, d_xt, b1, nullptr);

    dim3 g2(DIM / 256, NTOK / 128, NEXP);
    moe_mma<2><<<g2, 256, smem2>>>(d_w2t, d_H, b2, out);
}

// round 10
// speedup vs baseline: 3.7090x; 1.3083x over previous
#include <cuda_runtime.h>
#include <cuda_fp16.h>
#include <math.h>
#include <stdint.h>

#define NTOK 4096
#define DIM  1024
#define FDIM 4096
#define NEXP 8

// ---------------- scratch (static device globals; no allocation allowed) ----
__device__ float g_sn[NEXP * DIM];
__device__ float g_M[NEXP * DIM];            // fp32-exact gate numerator matrix
__device__ float g_norm2[NTOK];
__device__ int   g_topi[NTOK * 2];
__device__ float g_topw[NTOK * 2];
__device__ int   g_count[NEXP];
__device__ int   g_toklist[NEXP * NTOK];
__device__ float g_tokw[NEXP * NTOK];
// fp16 operands
__device__ __half g_xh[(size_t)NTOK * DIM];             // 8 MB
__device__ __half g_Wph[(size_t)DIM * DIM];             // 2 MB   [n][k]
__device__ __half g_W1h[(size_t)NEXP * FDIM * DIM];     // 64 MB  [e][F][k]  (transposed)
__device__ __half g_W2h[(size_t)NEXP * DIM * FDIM];     // 64 MB  [e][d][F]  (transposed)
__device__ __half g_Hh[(size_t)NEXP * NTOK * FDIM];     // 256 MB [e][m][F]

// ---------------- helpers ---------------------------------------------------
__device__ __forceinline__ uint32_t smem_u32(const void* p) {
    uint32_t a;
    asm("{ .reg .u64 t; cvta.to.shared.u64 t, %1; cvt.u32.u64 %0, t; }" : "=r"(a) : "l"(p));
    return a;
}
__device__ __forceinline__ void cp16(uint32_t dst, const void* src) {
    asm volatile("cp.async.cg.shared.global [%0], [%1], 16;" :: "r"(dst), "l"(src) : "memory");
}
__device__ __forceinline__ void cp_commit() {
    asm volatile("cp.async.commit_group;" ::: "memory");
}
__device__ __forceinline__ void cp_wait1() {
    asm volatile("cp.async.wait_group 1;" ::: "memory");
}
__device__ __forceinline__ void mma_f16(float* d, const uint32_t* a, const uint32_t* b) {
    asm volatile(
        "mma.sync.aligned.m16n8k16.row.col.f32.f16.f16.f32 "
        "{%0,%1,%2,%3}, {%4,%5,%6,%7}, {%8,%9}, {%0,%1,%2,%3};"
        : "+f"(d[0]), "+f"(d[1]), "+f"(d[2]), "+f"(d[3])
        : "r"(a[0]), "r"(a[1]), "r"(a[2]), "r"(a[3]), "r"(b[0]), "r"(b[1]));
}
__device__ __forceinline__ float gelu_exact(float v) {
    return 0.5f * v * (1.0f + erff(v * 0.70710678118654752440f));
}

// ---------------------------------------------------------------------------
__global__ void zero_kernel(float* __restrict__ out) {
    size_t i = (size_t)blockIdx.x * blockDim.x + threadIdx.x;
    if (i < (size_t)NTOK * DIM) out[i] = 0.0f;
    if (i < NTOK) g_norm2[i] = 0.0f;
    if (i < NEXP) g_count[i] = 0;
}

// fp32 -> fp16 elementwise (half2 granularity)
__global__ void cvth_kernel(const float* __restrict__ src, __half* __restrict__ dst, int n2) {
    int i = blockIdx.x * blockDim.x + threadIdx.x;
    if (i < n2) {
        float2 v = ((const float2*)src)[i];
        ((__half2*)dst)[i] = __floats2half2_rn(v.x, v.y);
    }
}

// src [e][Kd][Fd] fp32 -> dst [e][Fd][Kd] fp16  (tiled transpose)
__global__ void transp_kernel(const float* __restrict__ src, __half* __restrict__ dst,
                              int Kd, int Fd) {
    __shared__ float t[32][33];
    int e = blockIdx.z;
    const float* S = src + (size_t)e * Kd * Fd;
    __half* D = dst + (size_t)e * Kd * Fd;
    int f0 = blockIdx.x * 32, k0 = blockIdx.y * 32;
    int tx = threadIdx.x, ty = threadIdx.y;
    #pragma unroll
    for (int i = ty; i < 32; i += 8)
        t[i][tx] = S[(size_t)(k0 + i) * Fd + f0 + tx];
    __syncthreads();
    #pragma unroll
    for (int i = ty; i < 32; i += 8)
        D[(size_t)(f0 + i) * Kd + k0 + tx] = __float2half_rn(t[tx][i]);
}

__global__ void normsim_kernel(const float* __restrict__ sim) {
    int w = threadIdx.x >> 5, lane = threadIdx.x & 31;
    if (w >= NEXP) return;
    float ss = 0.0f;
    for (int k = lane; k < DIM; k += 32) { float v = sim[w * DIM + k]; ss += v * v; }
    #pragma unroll
    for (int off = 16; off; off >>= 1) ss += __shfl_xor_sync(0xffffffffu, ss, off);
    float inv = 1.0f / fmaxf(sqrtf(ss), 1e-12f);
    for (int k = lane; k < DIM; k += 32) g_sn[w * DIM + k] = sim[w * DIM + k] * inv;
}

// M[e][i] = sum_o Wp[o][i] * sn[e][o]   (fp32-exact gate numerators)
__global__ void gateM_kernel(const float* __restrict__ Wp) {
    int e = blockIdx.x;
    int i0 = threadIdx.x * 4;
    float4 acc = make_float4(0, 0, 0, 0);
    #pragma unroll 4
    for (int o = 0; o < DIM; o++) {
        float s = g_sn[e * DIM + o];
        float4 w = *(const float4*)(Wp + (size_t)o * DIM + i0);
        acc.x += s * w.x; acc.y += s * w.y; acc.z += s * w.z; acc.w += s * w.w;
    }
    *(float4*)(g_M + e * DIM + i0) = acc;
}

// one warp per token: fp32 dots x.M_e; |p| from fp16 norm (scale only); top2+softmax
__global__ void gate2_kernel(const float* __restrict__ x, const float* __restrict__ temp) {
    __shared__ float sM[NEXP][DIM];
    int tid = threadIdx.x;
    for (int i = tid; i < NEXP * DIM; i += 256) ((float*)sM)[i] = g_M[i];
    __syncthreads();
    int w = tid >> 5, lane = tid & 31;
    int t = blockIdx.x * 8 + w;
    const float4* xr = (const float4*)(x + (size_t)t * DIM);
    float acc[NEXP];
    #pragma unroll
    for (int e = 0; e < NEXP; e++) acc[e] = 0.0f;
    for (int k4 = lane; k4 < DIM / 4; k4 += 32) {
        float4 xv = xr[k4];
        #pragma unroll
        for (int e = 0; e < NEXP; e++) {
            float4 mv = *(const float4*)&sM[e][k4 * 4];
            acc[e] += xv.x * mv.x + xv.y * mv.y + xv.z * mv.z + xv.w * mv.w;
        }
    }
    #pragma unroll
    for (int off = 16; off; off >>= 1)
        #pragma unroll
        for (int e = 0; e < NEXP; e++) acc[e] += __shfl_xor_sync(0xffffffffu, acc[e], off);
    if (lane == 0) {
        float pn   = sqrtf(g_norm2[t]);
        float inv  = 1.0f / fmaxf(pn, 1e-12f);
        float tinv = 1.0f / temp[0];
        float sc[NEXP];
        #pragma unroll
        for (int e = 0; e < NEXP; e++) sc[e] = acc[e] * inv * tinv;
        int i0 = 0; float v0 = sc[0];
        #pragma unroll
        for (int e = 1; e < NEXP; e++) if (sc[e] > v0) { v0 = sc[e]; i0 = e; }
        int i1 = -1; float v1 = -1e30f;
        #pragma unroll
        for (int e = 0; e < NEXP; e++) if (e != i0 && sc[e] > v1) { v1 = sc[e]; i1 = e; }
        float e1 = expf(v1 - v0);
        float w0 = 1.0f / (1.0f + e1);
        g_topi[t * 2] = i0;  g_topi[t * 2 + 1] = i1;
        g_topw[t * 2] = w0;  g_topw[t * 2 + 1] = e1 * w0;
    }
}

__global__ void route_kernel() {
    int t = blockIdx.x * blockDim.x + threadIdx.x;
    if (t >= NTOK) return;
    #pragma unroll
    for (int k = 0; k < 2; k++) {
        int e = g_topi[t * 2 + k];
        int pos = atomicAdd(&g_count[e], 1);
        g_toklist[e * NTOK + pos] = t;
        g_tokw[e * NTOK + pos]    = g_topw[t * 2 + k];
    }
}

// ---------------------------------------------------------------------------
// fp16 m16n8k16 GEMM. CTA tile 256(tokens) x 128(features) x 64, 8 warps
// (4R x 2C), warp tile 64x64, cp.async 3-stage ring, one sync per chunk.
// All modes: A = K-major activation rows, B = K-major weight rows.
// MODE 0: A=xh[m][k],           B=Wph[n][k]   -> row-norm^2 (atomicAdd)
// MODE 1: A=xh[gather m][k],    B=W1h[e][F][k]-> Hh[e][m][F] = f16(gelu(.+b1))
// MODE 2: A=Hh[e][m][F],        B=W2h[e][d][F]-> out[tok][d] += wv*(.+b2)
// ---------------------------------------------------------------------------
template<int MODE>
__global__ __launch_bounds__(256)
void moe_hmma(const __half* __restrict__ Ab, const __half* __restrict__ Bb,
              const float* __restrict__ bias, float* __restrict__ out) {
    constexpr int K  = (MODE == 2) ? FDIM : DIM;
    constexpr int NB = (MODE == 1) ? FDIM : DIM;   // bias row length
    constexpr int RS = 72;                          // smem row stride (halfs)
    constexpr int A_H = 256 * RS;                   // halfs per A stage
    constexpr int B_H = 128 * RS;
    constexpr int STAGE_H = A_H + B_H;              // 27648 halfs = 55296 B

    extern __shared__ char smraw[];
    float* sBias = (float*)smraw;                   // 128 floats
    __half* smh = (__half*)(smraw + 1024);
    const uint32_t smb = smem_u32(smh);

    const int tid  = threadIdx.x;
    const int lane = tid & 31;
    const int wid  = tid >> 5;
    const int gid  = lane >> 2;
    const int tig  = lane & 3;
    const int R_warp = (wid & 3) * 64;
    const int C_warp = (wid >> 2) * 64;
    const int e = blockIdx.z;

    const int R0 = blockIdx.y * 256;
    const int C0 = blockIdx.x * 128;
    int M = NTOK;
    if (MODE != 0) {
        M = g_count[e];
        if (R0 >= M) return;
        if (tid < 128) sBias[tid] = bias[(size_t)e * NB + C0 + tid];
    }

    // ---- A copy: 8 rows/thread (row = tid>>3 + 32i), 16B seg (tid&7) ----
    const int arow  = tid >> 3;
    const int akoff = (tid & 7) * 8;                // halfs
    const __half* aP[8];
    uint32_t aDst[8];
    #pragma unroll
    for (int i = 0; i < 8; i++) {
        int r = arow + 32 * i;
        if (MODE == 0) {
            aP[i] = Ab + (size_t)(R0 + r) * DIM + akoff;
        } else if (MODE == 1) {
            int gm = R0 + r;
            int gr = (gm < M) ? g_toklist[e * NTOK + gm] : 0;
            aP[i] = Ab + (size_t)gr * DIM + akoff;
        } else {
            aP[i] = g_Hh + ((size_t)e * NTOK + R0 + r) * FDIM + akoff;
        }
        aDst[i] = (uint32_t)((r * RS + akoff) * 2);
    }
    // ---- B copy: row = tid>>1, 4 x 16B segs ----
    const int brow  = tid >> 1;
    const int bkoff = (tid & 1) * 32;               // halfs
    const __half* bP;
    if (MODE == 0)      bP = Bb + (size_t)(C0 + brow) * DIM + bkoff;
    else if (MODE == 1) bP = Bb + (size_t)e * FDIM * DIM + (size_t)(C0 + brow) * DIM + bkoff;
    else                bP = Bb + (size_t)e * DIM * FDIM + (size_t)(C0 + brow) * FDIM + bkoff;
    const uint32_t bDst = (uint32_t)((A_H + brow * RS + bkoff) * 2);

    auto issue = [&](int c, int s) {
        uint32_t sb = smb + (uint32_t)(s * STAGE_H * 2);
        int k0 = c * 64;
        #pragma unroll
        for (int i = 0; i < 8; i++) cp16(sb + aDst[i], aP[i] + k0);
        #pragma unroll
        for (int i = 0; i < 4; i++) cp16(sb + bDst + i * 16, bP + k0 + i * 8);
    };

    float acc[4][8][4];
    #pragma unroll
    for (int i = 0; i < 4; i++)
        #pragma unroll
        for (int j = 0; j < 8; j++)
            #pragma unroll
            for (int q = 0; q < 4; q++) acc[i][j][q] = 0.0f;

    constexpr int nch = K / 64;
    issue(0, 0); cp_commit();
    issue(1, 1); cp_commit();

    for (int c = 0; c < nch; ++c) {
        cp_wait1();
        __syncthreads();
        if (c + 2 < nch) issue(c + 2, (c + 2) % 3);
        cp_commit();

        const __half* base  = smh + (c % 3) * STAGE_H;
        const __half* bbase = base + A_H;
        #pragma unroll
        for (int kb = 0; kb < 4; kb++) {
            uint32_t af[4][4];
            #pragma unroll
            for (int rt = 0; rt < 4; rt++) {
                int r = R_warp + rt * 16 + gid;
                const uint32_t* p0 = (const uint32_t*)(base + r * RS + kb * 16 + 2 * tig);
                const uint32_t* p1 = (const uint32_t*)(base + (r + 8) * RS + kb * 16 + 2 * tig);
                af[rt][0] = p0[0]; af[rt][1] = p1[0];
                af[rt][2] = p0[4]; af[rt][3] = p1[4];
            }
            #pragma unroll
            for (int ct = 0; ct < 8; ct++) {
                int cc = C_warp + ct * 8 + gid;
                const uint32_t* pb = (const uint32_t*)(bbase + cc * RS + kb * 16 + 2 * tig);
                uint32_t bf[2] = { pb[0], pb[4] };
                #pragma unroll
                for (int rt = 0; rt < 4; rt++)
                    mma_f16(acc[rt][ct], af[rt], bf);
            }
        }
        // single sync per chunk; next top sync orders ring reuse
    }

    // ---- epilogue (D frag: [0]=(r,c) [1]=(r,c+1) [2]=(r+8,c) [3]=(r+8,c+1)) ----
    if (MODE == 0) {
        #pragma unroll
        for (int rt = 0; rt < 4; rt++) {
            float s0 = 0.0f, s1 = 0.0f;
            #pragma unroll
            for (int ct = 0; ct < 8; ct++) {
                s0 += acc[rt][ct][0] * acc[rt][ct][0] + acc[rt][ct][1] * acc[rt][ct][1];
                s1 += acc[rt][ct][2] * acc[rt][ct][2] + acc[rt][ct][3] * acc[rt][ct][3];
            }
            s0 += __shfl_xor_sync(0xffffffffu, s0, 1);
            s0 += __shfl_xor_sync(0xffffffffu, s0, 2);
            s1 += __shfl_xor_sync(0xffffffffu, s1, 1);
            s1 += __shfl_xor_sync(0xffffffffu, s1, 2);
            if (tig == 0) {
                int r = R0 + R_warp + rt * 16 + gid;
                atomicAdd(&g_norm2[r], s0);
                atomicAdd(&g_norm2[r + 8], s1);
            }
        }
    } else if (MODE == 1) {
        #pragma unroll
        for (int rt = 0; rt < 4; rt++) {
            int m = R0 + R_warp + rt * 16 + gid;
            __half* h0 = g_Hh + ((size_t)e * NTOK + m) * FDIM + C0;
            __half* h1 = h0 + (size_t)8 * FDIM;
            #pragma unroll
            for (int ct = 0; ct < 8; ct++) {
                int cl = C_warp + ct * 8 + 2 * tig;
                float b0 = sBias[cl], b1v = sBias[cl + 1];
                if (m < M)
                    *(__half2*)(h0 + cl) = __floats2half2_rn(
                        gelu_exact(acc[rt][ct][0] + b0), gelu_exact(acc[rt][ct][1] + b1v));
                if (m + 8 < M)
                    *(__half2*)(h1 + cl) = __floats2half2_rn(
                        gelu_exact(acc[rt][ct][2] + b0), gelu_exact(acc[rt][ct][3] + b1v));
            }
        }
    } else {
        #pragma unroll
        for (int rt = 0; rt < 4; rt++) {
            int m = R0 + R_warp + rt * 16 + gid;
            bool v0 = m < M, v1 = (m + 8) < M;
            int tok0 = 0, tok1 = 0; float wv0 = 0.f, wv1 = 0.f;
            if (v0) { tok0 = g_toklist[e * NTOK + m];     wv0 = g_tokw[e * NTOK + m]; }
            if (v1) { tok1 = g_toklist[e * NTOK + m + 8]; wv1 = g_tokw[e * NTOK + m + 8]; }
            #pragma unroll
            for (int ct = 0; ct < 8; ct++) {
                int cl = C_warp + ct * 8 + 2 * tig;
                int d  = C0 + cl;
                float b0 = sBias[cl], b1v = sBias[cl + 1];
                if (v0) {
                    float* o = out + (size_t)tok0 * DIM + d;
                    atomicAdd(&o[0], wv0 * (acc[rt][ct][0] + b0));
                    atomicAdd(&o[1], wv0 * (acc[rt][ct][1] + b1v));
                }
                if (v1) {
                    float* o = out + (size_t)tok1 * DIM + d;
                    atomicAdd(&o[0], wv1 * (acc[rt][ct][2] + b0));
                    atomicAdd(&o[1], wv1 * (acc[rt][ct][3] + b1v));
                }
            }
        }
    }
}

// ---------------------------------------------------------------------------
extern "C" void kernel_launch(void* const* d_in, const int* in_sizes, int n_in,
                              void* d_out, int out_size) {
    const float* x    = (const float*)d_in[0];
    const float* Wp   = (const float*)d_in[1];
    const float* sim  = (const float*)d_in[2];
    const float* temp = (const float*)d_in[3];
    const float* W1   = (const float*)d_in[4];
    const float* b1   = (const float*)d_in[5];
    const float* W2   = (const float*)d_in[6];
    const float* b2   = (const float*)d_in[7];
    float* out = (float*)d_out;

    const int smem = 1024 + 3 * (256 * 72 + 128 * 72) * 2;   // 166912
    cudaFuncSetAttribute(moe_hmma<0>, cudaFuncAttributeMaxDynamicSharedMemorySize, smem);
    cudaFuncSetAttribute(moe_hmma<1>, cudaFuncAttributeMaxDynamicSharedMemorySize, smem);
    cudaFuncSetAttribute(moe_hmma<2>, cudaFuncAttributeMaxDynamicSharedMemorySize, smem);

    __half* d_xh;  cudaGetSymbolAddress((void**)&d_xh,  g_xh);
    __half* d_wph; cudaGetSymbolAddress((void**)&d_wph, g_Wph);
    __half* d_w1h; cudaGetSymbolAddress((void**)&d_w1h, g_W1h);
    __half* d_w2h; cudaGetSymbolAddress((void**)&d_w2h, g_W2h);

    zero_kernel<<<(NTOK * DIM + 255) / 256, 256>>>(out);
    normsim_kernel<<<1, 256>>>(sim);
    gateM_kernel<<<NEXP, 256>>>(Wp);

    // operand conversion (one-time per launch)
    cvth_kernel<<<(NTOK * DIM / 2 + 255) / 256, 256>>>(x, d_xh, NTOK * DIM / 2);
    cvth_kernel<<<(DIM * DIM / 2 + 255) / 256, 256>>>(Wp, d_wph, DIM * DIM / 2);
    {
        dim3 b(32, 8);
        dim3 gt1(FDIM / 32, DIM / 32, NEXP);   // W1 [e][k=DIM][F=FDIM] -> [e][F][k]
        transp_kernel<<<gt1, b>>>(W1, d_w1h, DIM, FDIM);
        dim3 gt2(DIM / 32, FDIM / 32, NEXP);   // W2 [e][k=FDIM][d=DIM] -> [e][d][k]
        transp_kernel<<<gt2, b>>>(W2, d_w2h, FDIM, DIM);
    }

    dim3 g0(DIM / 128, NTOK / 256, 1);
    moe_hmma<0><<<g0, 256, smem>>>(d_xh, d_wph, nullptr, nullptr);

    gate2_kernel<<<NTOK / 8, 256>>>(x, temp);
    route_kernel<<<NTOK / 256, 256>>>();

    dim3 g1(FDIM / 128, NTOK / 256, NEXP);
    moe_hmma<1><<<g1, 256, smem>>>(d_xh, d_w1h, b1, nullptr);

    dim3 g2(DIM / 128, NTOK / 256, NEXP);
    moe_hmma<2><<<g2, 256, smem>>>(nullptr, d_w2h, b2, out);
}

// round 11
// speedup vs baseline: 3.9293x; 1.0594x over previous
#include <cuda_runtime.h>
#include <cuda_fp16.h>
#include <math.h>
#include <stdint.h>

#define NTOK 4096
#define DIM  1024
#define FDIM 4096
#define NEXP 8

// ---------------- scratch (static device globals; no allocation allowed) ----
__device__ float g_sn[NEXP * DIM];
__device__ float g_M[NEXP * DIM];            // fp32-exact gate numerator matrix
__device__ float g_norm2[NTOK];
__device__ int   g_topi[NTOK * 2];
__device__ float g_topw[NTOK * 2];
__device__ int   g_count[NEXP];
__device__ int   g_toklist[NEXP * NTOK];
__device__ float g_tokw[NEXP * NTOK];
// fp16 operands
__device__ __half g_xh[(size_t)NTOK * DIM];             // 8 MB
__device__ __half g_Wph[(size_t)DIM * DIM];             // 2 MB   [n][k]
__device__ __half g_W1h[(size_t)NEXP * FDIM * DIM];     // 64 MB  [e][F][k]  (transposed)
__device__ __half g_W2h[(size_t)NEXP * DIM * FDIM];     // 64 MB  [e][d][F]  (transposed)
__device__ __half g_Hh[(size_t)NEXP * NTOK * FDIM];     // 256 MB [e][m][F]

// ---------------- helpers ---------------------------------------------------
__device__ __forceinline__ uint32_t smem_u32(const void* p) {
    uint32_t a;
    asm("{ .reg .u64 t; cvta.to.shared.u64 t, %1; cvt.u32.u64 %0, t; }" : "=r"(a) : "l"(p));
    return a;
}
__device__ __forceinline__ void cp16(uint32_t dst, const void* src) {
    asm volatile("cp.async.cg.shared.global [%0], [%1], 16;" :: "r"(dst), "l"(src) : "memory");
}
__device__ __forceinline__ void cp_commit() {
    asm volatile("cp.async.commit_group;" ::: "memory");
}
__device__ __forceinline__ void cp_wait1() {
    asm volatile("cp.async.wait_group 1;" ::: "memory");
}
__device__ __forceinline__ void ldm_x4(uint32_t* r, uint32_t addr) {
    asm volatile("ldmatrix.sync.aligned.m8n8.x4.shared.b16 {%0,%1,%2,%3}, [%4];"
                 : "=r"(r[0]), "=r"(r[1]), "=r"(r[2]), "=r"(r[3]) : "r"(addr));
}
__device__ __forceinline__ void mma_f16(float* d, const uint32_t* a, const uint32_t* b) {
    asm volatile(
        "mma.sync.aligned.m16n8k16.row.col.f32.f16.f16.f32 "
        "{%0,%1,%2,%3}, {%4,%5,%6,%7}, {%8,%9}, {%0,%1,%2,%3};"
        : "+f"(d[0]), "+f"(d[1]), "+f"(d[2]), "+f"(d[3])
        : "r"(a[0]), "r"(a[1]), "r"(a[2]), "r"(a[3]), "r"(b[0]), "r"(b[1]));
}
__device__ __forceinline__ float gelu_exact(float v) {
    return 0.5f * v * (1.0f + erff(v * 0.70710678118654752440f));
}

// ---------------------------------------------------------------------------
__global__ void zero_kernel(float* __restrict__ out) {
    size_t i = (size_t)blockIdx.x * blockDim.x + threadIdx.x;
    if (i < (size_t)NTOK * DIM) out[i] = 0.0f;
    if (i < NTOK) g_norm2[i] = 0.0f;
    if (i < NEXP) g_count[i] = 0;
}

// fp32 -> fp16 elementwise (half2 granularity)
__global__ void cvth_kernel(const float* __restrict__ src, __half* __restrict__ dst, int n2) {
    int i = blockIdx.x * blockDim.x + threadIdx.x;
    if (i < n2) {
        float2 v = ((const float2*)src)[i];
        ((__half2*)dst)[i] = __floats2half2_rn(v.x, v.y);
    }
}

// src [e][Kd][Fd] fp32 -> dst [e][Fd][Kd] fp16  (tiled transpose)
__global__ void transp_kernel(const float* __restrict__ src, __half* __restrict__ dst,
                              int Kd, int Fd) {
    __shared__ float t[32][33];
    int e = blockIdx.z;
    const float* S = src + (size_t)e * Kd * Fd;
    __half* D = dst + (size_t)e * Kd * Fd;
    int f0 = blockIdx.x * 32, k0 = blockIdx.y * 32;
    int tx = threadIdx.x, ty = threadIdx.y;
    #pragma unroll
    for (int i = ty; i < 32; i += 8)
        t[i][tx] = S[(size_t)(k0 + i) * Fd + f0 + tx];
    __syncthreads();
    #pragma unroll
    for (int i = ty; i < 32; i += 8)
        D[(size_t)(f0 + i) * Kd + k0 + tx] = __float2half_rn(t[tx][i]);
}

__global__ void normsim_kernel(const float* __restrict__ sim) {
    int w = threadIdx.x >> 5, lane = threadIdx.x & 31;
    if (w >= NEXP) return;
    float ss = 0.0f;
    for (int k = lane; k < DIM; k += 32) { float v = sim[w * DIM + k]; ss += v * v; }
    #pragma unroll
    for (int off = 16; off; off >>= 1) ss += __shfl_xor_sync(0xffffffffu, ss, off);
    float inv = 1.0f / fmaxf(sqrtf(ss), 1e-12f);
    for (int k = lane; k < DIM; k += 32) g_sn[w * DIM + k] = sim[w * DIM + k] * inv;
}

// M[e][i] = sum_o Wp[o][i] * sn[e][o]   (fp32-exact gate numerators)
__global__ void gateM_kernel(const float* __restrict__ Wp) {
    int e = blockIdx.x;
    int i0 = threadIdx.x * 4;
    float4 acc = make_float4(0, 0, 0, 0);
    #pragma unroll 4
    for (int o = 0; o < DIM; o++) {
        float s = g_sn[e * DIM + o];
        float4 w = *(const float4*)(Wp + (size_t)o * DIM + i0);
        acc.x += s * w.x; acc.y += s * w.y; acc.z += s * w.z; acc.w += s * w.w;
    }
    *(float4*)(g_M + e * DIM + i0) = acc;
}

// one warp per token: fp32 dots x.M_e; |p| from fp16 norm (scale only); top2+softmax
__global__ void gate2_kernel(const float* __restrict__ x, const float* __restrict__ temp) {
    __shared__ float sM[NEXP][DIM];
    int tid = threadIdx.x;
    for (int i = tid; i < NEXP * DIM; i += 256) ((float*)sM)[i] = g_M[i];
    __syncthreads();
    int w = tid >> 5, lane = tid & 31;
    int t = blockIdx.x * 8 + w;
    const float4* xr = (const float4*)(x + (size_t)t * DIM);
    float acc[NEXP];
    #pragma unroll
    for (int e = 0; e < NEXP; e++) acc[e] = 0.0f;
    for (int k4 = lane; k4 < DIM / 4; k4 += 32) {
        float4 xv = xr[k4];
        #pragma unroll
        for (int e = 0; e < NEXP; e++) {
            float4 mv = *(const float4*)&sM[e][k4 * 4];
            acc[e] += xv.x * mv.x + xv.y * mv.y + xv.z * mv.z + xv.w * mv.w;
        }
    }
    #pragma unroll
    for (int off = 16; off; off >>= 1)
        #pragma unroll
        for (int e = 0; e < NEXP; e++) acc[e] += __shfl_xor_sync(0xffffffffu, acc[e], off);
    if (lane == 0) {
        float pn   = sqrtf(g_norm2[t]);
        float inv  = 1.0f / fmaxf(pn, 1e-12f);
        float tinv = 1.0f / temp[0];
        float sc[NEXP];
        #pragma unroll
        for (int e = 0; e < NEXP; e++) sc[e] = acc[e] * inv * tinv;
        int i0 = 0; float v0 = sc[0];
        #pragma unroll
        for (int e = 1; e < NEXP; e++) if (sc[e] > v0) { v0 = sc[e]; i0 = e; }
        int i1 = -1; float v1 = -1e30f;
        #pragma unroll
        for (int e = 0; e < NEXP; e++) if (e != i0 && sc[e] > v1) { v1 = sc[e]; i1 = e; }
        float e1 = expf(v1 - v0);
        float w0 = 1.0f / (1.0f + e1);
        g_topi[t * 2] = i0;  g_topi[t * 2 + 1] = i1;
        g_topw[t * 2] = w0;  g_topw[t * 2 + 1] = e1 * w0;
    }
}

__global__ void route_kernel() {
    int t = blockIdx.x * blockDim.x + threadIdx.x;
    if (t >= NTOK) return;
    #pragma unroll
    for (int k = 0; k < 2; k++) {
        int e = g_topi[t * 2 + k];
        int pos = atomicAdd(&g_count[e], 1);
        g_toklist[e * NTOK + pos] = t;
        g_tokw[e * NTOK + pos]    = g_topw[t * 2 + k];
    }
}

// ---------------------------------------------------------------------------
// fp16 m16n8k16 GEMM with ldmatrix fragment loads.
// CTA tile 256(tokens) x 128(features) x 64, 8 warps (4R x 2C), warp 64x64,
// cp.async 3-stage ring, one sync per chunk.
// MODE 0: A=xh[m][k],        B=Wph[n][k]    -> row-norm^2 (atomicAdd)
// MODE 1: A=xh[gather m][k], B=W1h[e][F][k] -> Hh[e][m][F] = f16(gelu(.+b1))
// MODE 2: A=Hh[e][m][F],     B=W2h[e][d][F] -> out[tok][d] += wv*(.+b2)
// ---------------------------------------------------------------------------
template<int MODE>
__global__ __launch_bounds__(256)
void moe_hmma(const __half* __restrict__ Ab, const __half* __restrict__ Bb,
              const float* __restrict__ bias, float* __restrict__ out) {
    constexpr int K  = (MODE == 2) ? FDIM : DIM;
    constexpr int NB = (MODE == 1) ? FDIM : DIM;   // bias row length
    constexpr int RS = 72;                          // smem row stride (halfs)
    constexpr int A_H = 256 * RS;                   // halfs per A stage
    constexpr int B_H = 128 * RS;
    constexpr int STAGE_H = A_H + B_H;

    extern __shared__ char smraw[];
    float* sBias = (float*)smraw;                   // 128 floats
    __half* smh = (__half*)(smraw + 1024);
    const uint32_t smb = smem_u32(smh);

    const int tid  = threadIdx.x;
    const int lane = tid & 31;
    const int wid  = tid >> 5;
    const int gid  = lane >> 2;
    const int tig  = lane & 3;
    const int R_warp = (wid & 3) * 64;
    const int C_warp = (wid >> 2) * 64;
    const int e = blockIdx.z;

    const int R0 = blockIdx.y * 256;
    const int C0 = blockIdx.x * 128;
    int M = NTOK;
    if (MODE != 0) {
        M = g_count[e];
        if (R0 >= M) return;
        if (tid < 128) sBias[tid] = bias[(size_t)e * NB + C0 + tid];
    }

    // ---- A copy: 8 rows/thread (row = tid>>3 + 32i), 16B seg (tid&7) ----
    const int arow  = tid >> 3;
    const int akoff = (tid & 7) * 8;                // halfs
    const __half* aP[8];
    uint32_t aDst[8];
    #pragma unroll
    for (int i = 0; i < 8; i++) {
        int r = arow + 32 * i;
        if (MODE == 0) {
            aP[i] = Ab + (size_t)(R0 + r) * DIM + akoff;
        } else if (MODE == 1) {
            int gm = R0 + r;
            int gr = (gm < M) ? g_toklist[e * NTOK + gm] : 0;
            aP[i] = Ab + (size_t)gr * DIM + akoff;
        } else {
            aP[i] = g_Hh + ((size_t)e * NTOK + R0 + r) * FDIM + akoff;
        }
        aDst[i] = (uint32_t)((r * RS + akoff) * 2);
    }
    // ---- B copy: row = tid>>1, 2 x 16B segs ----
    const int brow  = tid >> 1;
    const int bkoff = (tid & 1) * 32;               // halfs
    const __half* bP;
    if (MODE == 0)      bP = Bb + (size_t)(C0 + brow) * DIM + bkoff;
    else if (MODE == 1) bP = Bb + (size_t)e * FDIM * DIM + (size_t)(C0 + brow) * DIM + bkoff;
    else                bP = Bb + (size_t)e * DIM * FDIM + (size_t)(C0 + brow) * FDIM + bkoff;
    const uint32_t bDst = (uint32_t)((A_H + brow * RS + bkoff) * 2);

    auto issue = [&](int c, int s) {
        uint32_t sb = smb + (uint32_t)(s * STAGE_H * 2);
        int k0 = c * 64;
        #pragma unroll
        for (int i = 0; i < 8; i++) cp16(sb + aDst[i], aP[i] + k0);
        #pragma unroll
        for (int i = 0; i < 4; i++) cp16(sb + bDst + i * 16, bP + k0 + i * 8);
    };

    // ---- ldmatrix lane addressing (byte offsets within a stage) ----
    // A tiles (16x16 per rt): T0 r0-7/k0-7, T1 r8-15/k0-7, T2 r0-7/k8-15, T3 r8-15/k8-15
    const int l7  = lane & 7;
    const int l8  = (lane >> 3) & 1;
    const int l16 = (lane >> 4) & 1;
    uint32_t aLd[4], bLd[4];
    #pragma unroll
    for (int rt = 0; rt < 4; rt++)
        aLd[rt] = (uint32_t)(((R_warp + rt * 16 + l7 + l8 * 8) * RS + l16 * 8) * 2);
    // B tiles (16n x 16k per pair): T0 n0-7/k0-7, T1 n0-7/k8-15, T2 n8-15/k0-7, T3 n8-15/k8-15
    #pragma unroll
    for (int cp = 0; cp < 4; cp++)
        bLd[cp] = (uint32_t)((A_H + (C_warp + cp * 16 + l7 + l16 * 8) * RS + l8 * 8) * 2);

    float acc[4][8][4];
    #pragma unroll
    for (int i = 0; i < 4; i++)
        #pragma unroll
        for (int j = 0; j < 8; j++)
            #pragma unroll
            for (int q = 0; q < 4; q++) acc[i][j][q] = 0.0f;

    constexpr int nch = K / 64;
    issue(0, 0); cp_commit();
    issue(1, 1); cp_commit();

    for (int c = 0; c < nch; ++c) {
        cp_wait1();
        __syncthreads();
        if (c + 2 < nch) issue(c + 2, (c + 2) % 3);
        cp_commit();

        const uint32_t stb = smb + (uint32_t)((c % 3) * STAGE_H * 2);
        #pragma unroll
        for (int kb = 0; kb < 4; kb++) {
            const uint32_t kbo = kb * 32;           // 16 halfs = 32 bytes
            uint32_t af[4][4];
            #pragma unroll
            for (int rt = 0; rt < 4; rt++)
                ldm_x4(af[rt], stb + aLd[rt] + kbo);
            uint32_t bf[8][2];
            #pragma unroll
            for (int cp = 0; cp < 4; cp++) {
                uint32_t r[4];
                ldm_x4(r, stb + bLd[cp] + kbo);
                bf[2 * cp][0] = r[0];     bf[2 * cp][1] = r[1];
                bf[2 * cp + 1][0] = r[2]; bf[2 * cp + 1][1] = r[3];
            }
            #pragma unroll
            for (int ct = 0; ct < 8; ct++)
                #pragma unroll
                for (int rt = 0; rt < 4; rt++)
                    mma_f16(acc[rt][ct], af[rt], bf[ct]);
        }
        // single sync per chunk; next top sync orders ring reuse
    }

    // ---- epilogue (D frag: [0]=(r,c) [1]=(r,c+1) [2]=(r+8,c) [3]=(r+8,c+1)) ----
    if (MODE == 0) {
        #pragma unroll
        for (int rt = 0; rt < 4; rt++) {
            float s0 = 0.0f, s1 = 0.0f;
            #pragma unroll
            for (int ct = 0; ct < 8; ct++) {
                s0 += acc[rt][ct][0] * acc[rt][ct][0] + acc[rt][ct][1] * acc[rt][ct][1];
                s1 += acc[rt][ct][2] * acc[rt][ct][2] + acc[rt][ct][3] * acc[rt][ct][3];
            }
            s0 += __shfl_xor_sync(0xffffffffu, s0, 1);
            s0 += __shfl_xor_sync(0xffffffffu, s0, 2);
            s1 += __shfl_xor_sync(0xffffffffu, s1, 1);
            s1 += __shfl_xor_sync(0xffffffffu, s1, 2);
            if (tig == 0) {
                int r = R0 + R_warp + rt * 16 + gid;
                atomicAdd(&g_norm2[r], s0);
                atomicAdd(&g_norm2[r + 8], s1);
            }
        }
    } else if (MODE == 1) {
        #pragma unroll
        for (int rt = 0; rt < 4; rt++) {
            int m = R0 + R_warp + rt * 16 + gid;
            __half* h0 = g_Hh + ((size_t)e * NTOK + m) * FDIM + C0;
            __half* h1 = h0 + (size_t)8 * FDIM;
            #pragma unroll
            for (int ct = 0; ct < 8; ct++) {
                int cl = C_warp + ct * 8 + 2 * tig;
                float b0 = sBias[cl], b1v = sBias[cl + 1];
                if (m < M)
                    *(__half2*)(h0 + cl) = __floats2half2_rn(
                        gelu_exact(acc[rt][ct][0] + b0), gelu_exact(acc[rt][ct][1] + b1v));
                if (m + 8 < M)
                    *(__half2*)(h1 + cl) = __floats2half2_rn(
                        gelu_exact(acc[rt][ct][2] + b0), gelu_exact(acc[rt][ct][3] + b1v));
            }
        }
    } else {
        #pragma unroll
        for (int rt = 0; rt < 4; rt++) {
            int m = R0 + R_warp + rt * 16 + gid;
            bool v0 = m < M, v1 = (m + 8) < M;
            int tok0 = 0, tok1 = 0; float wv0 = 0.f, wv1 = 0.f;
            if (v0) { tok0 = g_toklist[e * NTOK + m];     wv0 = g_tokw[e * NTOK + m]; }
            if (v1) { tok1 = g_toklist[e * NTOK + m + 8]; wv1 = g_tokw[e * NTOK + m + 8]; }
            #pragma unroll
            for (int ct = 0; ct < 8; ct++) {
                int cl = C_warp + ct * 8 + 2 * tig;
                int d  = C0 + cl;
                float b0 = sBias[cl], b1v = sBias[cl + 1];
                if (v0) {
                    float* o = out + (size_t)tok0 * DIM + d;
                    atomicAdd(&o[0], wv0 * (acc[rt][ct][0] + b0));
                    atomicAdd(&o[1], wv0 * (acc[rt][ct][1] + b1v));
                }
                if (v1) {
                    float* o = out + (size_t)tok1 * DIM + d;
                    atomicAdd(&o[0], wv1 * (acc[rt][ct][2] + b0));
                    atomicAdd(&o[1], wv1 * (acc[rt][ct][3] + b1v));
                }
            }
        }
    }
}

// ---------------------------------------------------------------------------
extern "C" void kernel_launch(void* const* d_in, const int* in_sizes, int n_in,
                              void* d_out, int out_size) {
    const float* x    = (const float*)d_in[0];
    const float* Wp   = (const float*)d_in[1];
    const float* sim  = (const float*)d_in[2];
    const float* temp = (const float*)d_in[3];
    const float* W1   = (const float*)d_in[4];
    const float* b1   = (const float*)d_in[5];
    const float* W2   = (const float*)d_in[6];
    const float* b2   = (const float*)d_in[7];
    float* out = (float*)d_out;

    const int smem = 1024 + 3 * (256 * 72 + 128 * 72) * 2;   // 166912
    cudaFuncSetAttribute(moe_hmma<0>, cudaFuncAttributeMaxDynamicSharedMemorySize, smem);
    cudaFuncSetAttribute(moe_hmma<1>, cudaFuncAttributeMaxDynamicSharedMemorySize, smem);
    cudaFuncSetAttribute(moe_hmma<2>, cudaFuncAttributeMaxDynamicSharedMemorySize, smem);

    __half* d_xh;  cudaGetSymbolAddress((void**)&d_xh,  g_xh);
    __half* d_wph; cudaGetSymbolAddress((void**)&d_wph, g_Wph);
    __half* d_w1h; cudaGetSymbolAddress((void**)&d_w1h, g_W1h);
    __half* d_w2h; cudaGetSymbolAddress((void**)&d_w2h, g_W2h);

    zero_kernel<<<(NTOK * DIM + 255) / 256, 256>>>(out);
    normsim_kernel<<<1, 256>>>(sim);
    gateM_kernel<<<NEXP, 256>>>(Wp);

    // operand conversion (one-time per launch)
    cvth_kernel<<<(NTOK * DIM / 2 + 255) / 256, 256>>>(x, d_xh, NTOK * DIM / 2);
    cvth_kernel<<<(DIM * DIM / 2 + 255) / 256, 256>>>(Wp, d_wph, DIM * DIM / 2);
    {
        dim3 b(32, 8);
        dim3 gt1(FDIM / 32, DIM / 32, NEXP);   // W1 [e][k=DIM][F=FDIM] -> [e][F][k]
        transp_kernel<<<gt1, b>>>(W1, d_w1h, DIM, FDIM);
        dim3 gt2(DIM / 32, FDIM / 32, NEXP);   // W2 [e][k=FDIM][d=DIM] -> [e][d][k]
        transp_kernel<<<gt2, b>>>(W2, d_w2h, FDIM, DIM);
    }

    dim3 g0(DIM / 128, NTOK / 256, 1);
    moe_hmma<0><<<g0, 256, smem>>>(d_xh, d_wph, nullptr, nullptr);

    gate2_kernel<<<NTOK / 8, 256>>>(x, temp);
    route_kernel<<<NTOK / 256, 256>>>();

    dim3 g1(FDIM / 128, NTOK / 256, NEXP);
    moe_hmma<1><<<g1, 256, smem>>>(d_xh, d_w1h, b1, nullptr);

    dim3 g2(DIM / 128, NTOK / 256, NEXP);
    moe_hmma<2><<<g2, 256, smem>>>(nullptr, d_w2h, b2, out);
}